// round 1
// baseline (speedup 1.0000x reference)
#include <cuda_runtime.h>

#define NN 100000
#define EMAX 1700000

// ---------------- scratch (static device globals; no allocs) ----------------
__device__ float    g_h1[NN * 64];   // layer1 pre-attention features
__device__ float    g_x1[NN * 64];   // layer1 aggregated -> relu'd (input to layer2)
__device__ float    g_h2[NN * 32];   // layer2 pre-attention features
__device__ float    g_x2[NN * 32];   // layer2 aggregated -> relu'd
__device__ float    g_as[NN];
__device__ float    g_ad[NN];
__device__ unsigned g_m[NN];         // segment max, monotone-encoded float
__device__ float    g_den[NN];
__device__ float    g_ex[EMAX];

// monotone float<->uint encoding so atomicMax(unsigned) == float max
__device__ __forceinline__ unsigned fenc(float f) {
    unsigned u = __float_as_uint(f);
    return (u & 0x80000000u) ? ~u : (u | 0x80000000u);
}
__device__ __forceinline__ float fdec(unsigned u) {
    return (u & 0x80000000u) ? __uint_as_float(u & 0x7FFFFFFFu)
                             : __uint_as_float(~u);
}

// ---------------- fill kernels ----------------
__global__ void fill_f32(float* p, float v, int n) {
    int i = blockIdx.x * blockDim.x + threadIdx.x;
    if (i < n) p[i] = v;
}
__global__ void fill_u32(unsigned* p, unsigned v, int n) {
    int i = blockIdx.x * blockDim.x + threadIdx.x;
    if (i < n) p[i] = v;
}

// ---------------- tiled fp32 GEMM: C[M,N] = A[M,K] @ B[K,N] ----------------
// BN == N exactly; K % BK == 0; TN == 4 (float4 stores)
template <int BM, int BN, int BK, int TM, int TN>
__global__ void gemm_kernel(const float* __restrict__ A,
                            const float* __restrict__ B,
                            float* __restrict__ C, int M, int N, int K) {
    __shared__ float As[BK][BM + 4];
    __shared__ float Bs[BK][BN];
    const int tx = threadIdx.x, ty = threadIdx.y;
    const int tid = ty * blockDim.x + tx;
    constexpr int NT = (BM / TM) * (BN / TN);
    const int rowBase = blockIdx.x * BM;

    float acc[TM][TN];
#pragma unroll
    for (int i = 0; i < TM; i++)
#pragma unroll
        for (int j = 0; j < TN; j++) acc[i][j] = 0.f;

    for (int k0 = 0; k0 < K; k0 += BK) {
        // load A tile (BM x BK), transposed into smem
#pragma unroll
        for (int it = tid; it < BM * BK / 4; it += NT) {
            int r = (it * 4) / BK, c = (it * 4) % BK;
            float4 v = make_float4(0.f, 0.f, 0.f, 0.f);
            int gr = rowBase + r;
            if (gr < M) v = *(const float4*)(A + (size_t)gr * K + k0 + c);
            As[c + 0][r] = v.x; As[c + 1][r] = v.y;
            As[c + 2][r] = v.z; As[c + 3][r] = v.w;
        }
        // load B tile (BK x BN)
#pragma unroll
        for (int it = tid; it < BK * BN / 4; it += NT) {
            int r = (it * 4) / BN, c = (it * 4) % BN;
            *(float4*)&Bs[r][c] = *(const float4*)(B + (size_t)(k0 + r) * N + c);
        }
        __syncthreads();
#pragma unroll
        for (int k = 0; k < BK; k++) {
            float ra[TM], rb[TN];
#pragma unroll
            for (int i = 0; i < TM; i++) ra[i] = As[k][ty * TM + i];
#pragma unroll
            for (int j = 0; j < TN; j++) rb[j] = Bs[k][tx * TN + j];
#pragma unroll
            for (int i = 0; i < TM; i++)
#pragma unroll
                for (int j = 0; j < TN; j++) acc[i][j] += ra[i] * rb[j];
        }
        __syncthreads();
    }
#pragma unroll
    for (int i = 0; i < TM; i++) {
        int gr = rowBase + ty * TM + i;
        if (gr < M)
            *(float4*)(C + (size_t)gr * N + tx * TN) =
                make_float4(acc[i][0], acc[i][1], acc[i][2], acc[i][3]);
    }
}

// ---------------- per-node alpha dots ----------------
template <int H>
__global__ void alpha_kernel(const float* __restrict__ h,
                             const float* __restrict__ av,
                             const float* __restrict__ bv,
                             float* __restrict__ as, float* __restrict__ ad,
                             int n) {
    int i = blockIdx.x * blockDim.x + threadIdx.x;
    if (i >= n) return;
    const float4* hp = (const float4*)(h + (size_t)i * H);
    float s = 0.f, d = 0.f;
#pragma unroll
    for (int j = 0; j < H / 4; j++) {
        float4 hv = hp[j];
        float4 a = ((const float4*)av)[j];
        float4 b = ((const float4*)bv)[j];
        s += hv.x * a.x + hv.y * a.y + hv.z * a.z + hv.w * a.w;
        d += hv.x * b.x + hv.y * b.y + hv.z * b.z + hv.w * b.w;
    }
    as[i] = s;
    ad[i] = d;
}

// ---------------- edge pass A: segment max ----------------
__global__ void edge_max_kernel(const int* __restrict__ ei, int E, int nE,
                                const float* __restrict__ as,
                                const float* __restrict__ ad,
                                unsigned* __restrict__ m) {
    int e = blockIdx.x * blockDim.x + threadIdx.x;
    if (e >= nE) return;
    int s, d;
    if (e < E) { s = ei[e]; d = ei[E + e]; } else { s = d = e - E; }
    float v = as[s] + ad[d];
    v = (v > 0.f) ? v : 0.2f * v;
    atomicMax(&m[d], fenc(v));
}

// ---------------- edge pass B: exp + denom ----------------
__global__ void edge_exp_kernel(const int* __restrict__ ei, int E, int nE,
                                const float* __restrict__ as,
                                const float* __restrict__ ad,
                                const unsigned* __restrict__ m,
                                float* __restrict__ den,
                                float* __restrict__ ex) {
    int e = blockIdx.x * blockDim.x + threadIdx.x;
    if (e >= nE) return;
    int s, d;
    if (e < E) { s = ei[e]; d = ei[E + e]; } else { s = d = e - E; }
    float v = as[s] + ad[d];
    v = (v > 0.f) ? v : 0.2f * v;
    float mx = fdec(m[d]);
    float x = __expf(v - mx);
    ex[e] = x;
    atomicAdd(&den[d], x);
}

// ---------------- edge pass C: weighted scatter-add of features ----------------
template <int H>
__global__ void edge_agg_kernel(const int* __restrict__ ei, int E, int nE,
                                const float* __restrict__ ex,
                                const float* __restrict__ den,
                                const float* __restrict__ h,
                                float* __restrict__ agg) {
    constexpr int G = H / 4;  // threads per edge, one float4 each
    int t = blockIdx.x * blockDim.x + threadIdx.x;
    int e = t / G;
    int lane = t % G;
    if (e >= nE) return;
    int s, d;
    if (e < E) { s = ei[e]; d = ei[E + e]; } else { s = d = e - E; }
    float attn = ex[e] / den[d];
    float4 hv = ((const float4*)(h + (size_t)s * H))[lane];
    float4 v = make_float4(hv.x * attn, hv.y * attn, hv.z * attn, hv.w * attn);
    float* p = agg + (size_t)d * H + lane * 4;
    asm volatile("red.global.add.v4.f32 [%0], {%1, %2, %3, %4};" ::"l"(p),
                 "f"(v.x), "f"(v.y), "f"(v.z), "f"(v.w)
                 : "memory");
}

// ---------------- bias + relu (in place) ----------------
__global__ void bias_relu_kernel(float* __restrict__ x,
                                 const float* __restrict__ b, int H,
                                 int total) {
    int i = blockIdx.x * blockDim.x + threadIdx.x;
    if (i >= total) return;
    float v = x[i] + b[i % H];
    x[i] = (v > 0.f) ? v : 0.f;
}

// ---------------- final: out[i] = h2[i] . Wfc + bfc ----------------
__global__ void final_kernel(const float* __restrict__ h,
                             const float* __restrict__ Wfc,
                             const float* __restrict__ bfc,
                             float* __restrict__ out, int n) {
    int i = blockIdx.x * blockDim.x + threadIdx.x;
    if (i >= n) return;
    const float4* hp = (const float4*)(h + (size_t)i * 32);
    float s = 0.f;
#pragma unroll
    for (int j = 0; j < 8; j++) {
        float4 a = hp[j];
        float4 w = ((const float4*)Wfc)[j];
        s += a.x * w.x + a.y * w.y + a.z * w.z + a.w * w.w;
    }
    out[i] = s + bfc[0];
}

// ---------------- launch ----------------
extern "C" void kernel_launch(void* const* d_in, const int* in_sizes, int n_in,
                              void* d_out, int out_size) {
    const float* x   = (const float*)d_in[0];
    const int*   ei  = (const int*)d_in[1];
    const float* W1  = (const float*)d_in[2];
    const float* as1 = (const float*)d_in[3];
    const float* ad1 = (const float*)d_in[4];
    const float* b1  = (const float*)d_in[5];
    const float* W2  = (const float*)d_in[6];
    const float* as2 = (const float*)d_in[7];
    const float* ad2 = (const float*)d_in[8];
    const float* b2  = (const float*)d_in[9];
    const float* Wfc = (const float*)d_in[10];
    const float* bfc = (const float*)d_in[11];
    float* out = (float*)d_out;

    const int N  = in_sizes[0] / 256;  // 100000
    const int E  = in_sizes[1] / 2;    // 1600000
    const int ET = E + N;              // with self loops

    float *h1, *x1, *h2, *x2, *asb, *adb, *den, *ex;
    unsigned* m;
    cudaGetSymbolAddress((void**)&h1, g_h1);
    cudaGetSymbolAddress((void**)&x1, g_x1);
    cudaGetSymbolAddress((void**)&h2, g_h2);
    cudaGetSymbolAddress((void**)&x2, g_x2);
    cudaGetSymbolAddress((void**)&asb, g_as);
    cudaGetSymbolAddress((void**)&adb, g_ad);
    cudaGetSymbolAddress((void**)&m, g_m);
    cudaGetSymbolAddress((void**)&den, g_den);
    cudaGetSymbolAddress((void**)&ex, g_ex);

    const int T = 256;
    auto nb = [](long long n, int t) { return (int)((n + t - 1) / t); };

    // ---------- layer 1 (H=64) ----------
    gemm_kernel<128, 64, 16, 8, 4>
        <<<nb(N, 128), dim3(16, 16)>>>(x, W1, h1, N, 64, 256);
    alpha_kernel<64><<<nb(N, T), T>>>(h1, as1, ad1, asb, adb, N);
    fill_u32<<<nb(N, T), T>>>(m, 0u, N);
    fill_f32<<<nb(N, T), T>>>(den, 0.f, N);
    fill_f32<<<nb((long long)N * 64, T), T>>>(x1, 0.f, N * 64);
    edge_max_kernel<<<nb(ET, T), T>>>(ei, E, ET, asb, adb, m);
    edge_exp_kernel<<<nb(ET, T), T>>>(ei, E, ET, asb, adb, m, den, ex);
    edge_agg_kernel<64>
        <<<nb((long long)ET * 16, T), T>>>(ei, E, ET, ex, den, h1, x1);
    bias_relu_kernel<<<nb((long long)N * 64, T), T>>>(x1, b1, 64, N * 64);

    // ---------- layer 2 (H=32) ----------
    gemm_kernel<128, 32, 16, 8, 4>
        <<<nb(N, 128), dim3(8, 16)>>>(x1, W2, h2, N, 32, 64);
    alpha_kernel<32><<<nb(N, T), T>>>(h2, as2, ad2, asb, adb, N);
    fill_u32<<<nb(N, T), T>>>(m, 0u, N);
    fill_f32<<<nb(N, T), T>>>(den, 0.f, N);
    fill_f32<<<nb((long long)N * 32, T), T>>>(x2, 0.f, N * 32);
    edge_max_kernel<<<nb(ET, T), T>>>(ei, E, ET, asb, adb, m);
    edge_exp_kernel<<<nb(ET, T), T>>>(ei, E, ET, asb, adb, m, den, ex);
    edge_agg_kernel<32>
        <<<nb((long long)ET * 8, T), T>>>(ei, E, ET, ex, den, h2, x2);
    bias_relu_kernel<<<nb((long long)N * 32, T), T>>>(x2, b2, 32, N * 32);

    // ---------- head ----------
    final_kernel<<<nb(N, T), T>>>(x2, Wfc, bfc, out, N);
}

// round 2
// speedup vs baseline: 1.1494x; 1.1494x over previous
#include <cuda_runtime.h>

#define NN 100000

// ---------------- scratch (static device globals; no allocs) ----------------
__device__ float g_h1[NN * 64];   // layer1 pre-attention features
__device__ float g_x1[NN * 64];   // layer1 aggregated -> relu'd (input to layer2)
__device__ float g_h2[NN * 32];   // layer2 pre-attention features
__device__ float g_x2[NN * 32];   // layer2 aggregated -> relu'd
__device__ float g_as[NN];
__device__ float g_ad[NN];
__device__ float g_den[NN];

// ---------------- fill kernel ----------------
__global__ void fill_f32(float* p, float v, int n) {
    int i = blockIdx.x * blockDim.x + threadIdx.x;
    if (i < n) p[i] = v;
}

// ---------------- tiled fp32 GEMM: C[M,N] = A[M,K] @ B[K,N] ----------------
// BN == N exactly; K % BK == 0; TN == 4 (float4 stores)
template <int BM, int BN, int BK, int TM, int TN>
__global__ void gemm_kernel(const float* __restrict__ A,
                            const float* __restrict__ B,
                            float* __restrict__ C, int M, int N, int K) {
    __shared__ float As[BK][BM + 4];
    __shared__ float Bs[BK][BN];
    const int tx = threadIdx.x, ty = threadIdx.y;
    const int tid = ty * blockDim.x + tx;
    constexpr int NT = (BM / TM) * (BN / TN);
    const int rowBase = blockIdx.x * BM;

    float acc[TM][TN];
#pragma unroll
    for (int i = 0; i < TM; i++)
#pragma unroll
        for (int j = 0; j < TN; j++) acc[i][j] = 0.f;

    for (int k0 = 0; k0 < K; k0 += BK) {
#pragma unroll
        for (int it = tid; it < BM * BK / 4; it += NT) {
            int r = (it * 4) / BK, c = (it * 4) % BK;
            float4 v = make_float4(0.f, 0.f, 0.f, 0.f);
            int gr = rowBase + r;
            if (gr < M) v = *(const float4*)(A + (size_t)gr * K + k0 + c);
            As[c + 0][r] = v.x; As[c + 1][r] = v.y;
            As[c + 2][r] = v.z; As[c + 3][r] = v.w;
        }
#pragma unroll
        for (int it = tid; it < BK * BN / 4; it += NT) {
            int r = (it * 4) / BN, c = (it * 4) % BN;
            *(float4*)&Bs[r][c] = *(const float4*)(B + (size_t)(k0 + r) * N + c);
        }
        __syncthreads();
#pragma unroll
        for (int k = 0; k < BK; k++) {
            float ra[TM], rb[TN];
#pragma unroll
            for (int i = 0; i < TM; i++) ra[i] = As[k][ty * TM + i];
#pragma unroll
            for (int j = 0; j < TN; j++) rb[j] = Bs[k][tx * TN + j];
#pragma unroll
            for (int i = 0; i < TM; i++)
#pragma unroll
                for (int j = 0; j < TN; j++) acc[i][j] += ra[i] * rb[j];
        }
        __syncthreads();
    }
#pragma unroll
    for (int i = 0; i < TM; i++) {
        int gr = rowBase + ty * TM + i;
        if (gr < M)
            *(float4*)(C + (size_t)gr * N + tx * TN) =
                make_float4(acc[i][0], acc[i][1], acc[i][2], acc[i][3]);
    }
}

// ---------------- per-node alpha dots ----------------
template <int H>
__global__ void alpha_kernel(const float* __restrict__ h,
                             const float* __restrict__ av,
                             const float* __restrict__ bv,
                             float* __restrict__ as, float* __restrict__ ad,
                             int n) {
    int i = blockIdx.x * blockDim.x + threadIdx.x;
    if (i >= n) return;
    const float4* hp = (const float4*)(h + (size_t)i * H);
    float s = 0.f, d = 0.f;
#pragma unroll
    for (int j = 0; j < H / 4; j++) {
        float4 hv = hp[j];
        float4 a = ((const float4*)av)[j];
        float4 b = ((const float4*)bv)[j];
        s += hv.x * a.x + hv.y * a.y + hv.z * a.z + hv.w * a.w;
        d += hv.x * b.x + hv.y * b.y + hv.z * b.z + hv.w * b.w;
    }
    as[i] = s;
    ad[i] = d;
}

// ---------------- fused edge pass: w=exp(leakyrelu(e)); den += w; agg += w*h[s]
template <int H>
__global__ void edge_fused_kernel(const int* __restrict__ ei, int E, int nE,
                                  const float* __restrict__ as,
                                  const float* __restrict__ ad,
                                  const float* __restrict__ h,
                                  float* __restrict__ den,
                                  float* __restrict__ agg) {
    constexpr int G = H / 4;  // threads per edge, one float4 each
    int t = blockIdx.x * blockDim.x + threadIdx.x;
    int e = t / G;
    int lane = t % G;
    if (e >= nE) return;
    int s, d;
    if (e < E) { s = __ldg(&ei[e]); d = __ldg(&ei[E + e]); } else { s = d = e - E; }
    float v = __ldg(&as[s]) + __ldg(&ad[d]);
    v = (v > 0.f) ? v : 0.2f * v;
    float w = __expf(v);
    if (lane == 0) atomicAdd(&den[d], w);
    float4 hv = __ldg(&((const float4*)(h + (size_t)s * H))[lane]);
    float4 o = make_float4(hv.x * w, hv.y * w, hv.z * w, hv.w * w);
    float* p = agg + (size_t)d * H + lane * 4;
    asm volatile("red.global.add.v4.f32 [%0], {%1, %2, %3, %4};" ::"l"(p),
                 "f"(o.x), "f"(o.y), "f"(o.z), "f"(o.w)
                 : "memory");
}

// ---------------- normalize + bias + relu ----------------
template <int H>
__global__ void norm_bias_relu_kernel(float* __restrict__ x,
                                      const float* __restrict__ den,
                                      const float* __restrict__ b, int total) {
    int i = blockIdx.x * blockDim.x + threadIdx.x;
    if (i >= total) return;
    int node = i / H, col = i % H;
    float v = x[i] / den[node] + b[col];
    x[i] = (v > 0.f) ? v : 0.f;
}

// ---------------- final: out[i] = h2[i] . Wfc + bfc ----------------
__global__ void final_kernel(const float* __restrict__ h,
                             const float* __restrict__ Wfc,
                             const float* __restrict__ bfc,
                             float* __restrict__ out, int n) {
    int i = blockIdx.x * blockDim.x + threadIdx.x;
    if (i >= n) return;
    const float4* hp = (const float4*)(h + (size_t)i * 32);
    float s = 0.f;
#pragma unroll
    for (int j = 0; j < 8; j++) {
        float4 a = hp[j];
        float4 w = ((const float4*)Wfc)[j];
        s += a.x * w.x + a.y * w.y + a.z * w.z + a.w * w.w;
    }
    out[i] = s + bfc[0];
}

// ---------------- launch ----------------
extern "C" void kernel_launch(void* const* d_in, const int* in_sizes, int n_in,
                              void* d_out, int out_size) {
    const float* x   = (const float*)d_in[0];
    const int*   ei  = (const int*)d_in[1];
    const float* W1  = (const float*)d_in[2];
    const float* as1 = (const float*)d_in[3];
    const float* ad1 = (const float*)d_in[4];
    const float* b1  = (const float*)d_in[5];
    const float* W2  = (const float*)d_in[6];
    const float* as2 = (const float*)d_in[7];
    const float* ad2 = (const float*)d_in[8];
    const float* b2  = (const float*)d_in[9];
    const float* Wfc = (const float*)d_in[10];
    const float* bfc = (const float*)d_in[11];
    float* out = (float*)d_out;

    const int N  = in_sizes[0] / 256;  // 100000
    const int E  = in_sizes[1] / 2;    // 1600000
    const int ET = E + N;              // with self loops

    float *h1, *x1, *h2, *x2, *asb, *adb, *den;
    cudaGetSymbolAddress((void**)&h1, g_h1);
    cudaGetSymbolAddress((void**)&x1, g_x1);
    cudaGetSymbolAddress((void**)&h2, g_h2);
    cudaGetSymbolAddress((void**)&x2, g_x2);
    cudaGetSymbolAddress((void**)&asb, g_as);
    cudaGetSymbolAddress((void**)&adb, g_ad);
    cudaGetSymbolAddress((void**)&den, g_den);

    const int T = 256;
    auto nb = [](long long n, int t) { return (int)((n + t - 1) / t); };

    // ---------- layer 1 (H=64) ----------
    gemm_kernel<128, 64, 16, 8, 4>
        <<<nb(N, 128), dim3(16, 16)>>>(x, W1, h1, N, 64, 256);
    alpha_kernel<64><<<nb(N, T), T>>>(h1, as1, ad1, asb, adb, N);
    fill_f32<<<nb(N, T), T>>>(den, 0.f, N);
    fill_f32<<<nb((long long)N * 64, T), T>>>(x1, 0.f, N * 64);
    edge_fused_kernel<64>
        <<<nb((long long)ET * 16, T), T>>>(ei, E, ET, asb, adb, h1, den, x1);
    norm_bias_relu_kernel<64>
        <<<nb((long long)N * 64, T), T>>>(x1, den, b1, N * 64);

    // ---------- layer 2 (H=32) ----------
    gemm_kernel<128, 32, 16, 8, 4>
        <<<nb(N, 128), dim3(8, 16)>>>(x1, W2, h2, N, 32, 64);
    alpha_kernel<32><<<nb(N, T), T>>>(h2, as2, ad2, asb, adb, N);
    fill_f32<<<nb(N, T), T>>>(den, 0.f, N);
    fill_f32<<<nb((long long)N * 32, T), T>>>(x2, 0.f, N * 32);
    edge_fused_kernel<32>
        <<<nb((long long)ET * 8, T), T>>>(ei, E, ET, asb, adb, h2, den, x2);
    norm_bias_relu_kernel<32>
        <<<nb((long long)N * 32, T), T>>>(x2, den, b2, N * 32);

    // ---------- head ----------
    final_kernel<<<nb(N, T), T>>>(x2, Wfc, bfc, out, N);
}

// round 3
// speedup vs baseline: 1.1830x; 1.0292x over previous
#include <cuda_runtime.h>

#define NN 100000

// ---------------- scratch (static device globals; no allocs) ----------------
__device__ float g_h1[NN * 64];   // layer1 pre-attention features
__device__ float g_x1[NN * 64];   // layer1 aggregated (raw, pre-norm)
__device__ float g_h2[NN * 32];   // layer2 pre-attention features
__device__ float g_x2[NN * 32];   // layer2 aggregated (raw, pre-norm)
__device__ float g_as[NN];
__device__ float g_ad[NN];
__device__ float g_den[NN];

typedef unsigned long long u64;

__device__ __forceinline__ u64 ffma2(u64 a, u64 b, u64 c) {
    u64 d;
    asm("fma.rn.f32x2 %0, %1, %2, %3;" : "=l"(d) : "l"(a), "l"(b), "l"(c));
    return d;
}
__device__ __forceinline__ u64 pack2(float x, float y) {
    u64 r;
    asm("mov.b64 %0, {%1,%2};" : "=l"(r) : "f"(x), "f"(y));
    return r;
}
__device__ __forceinline__ void unpack2(u64 v, float& x, float& y) {
    asm("mov.b64 {%0,%1}, %2;" : "=f"(x), "=f"(y) : "l"(v));
}

// ---------------- fused GEMM: C[M,BN] = A[M,K] @ B[K,BN] -------------------
// Optional A transform: a = relu(a / dnorm[row] + bias[col])  (prev layer's
// normalize+bias+relu, folded into the single read of A).
// Optional alpha epilogue: as_out[r] = C[r,:].av ; ad_out[r] = C[r,:].bv
// BN == N exactly. TN == 8 (4 f32x2 per thread-col). blockDim = (BN/TN, BM/TM)
template <int BM, int BN, int BK, int TM, int TN, bool TRANSFORM, bool ALPHA>
__global__ void gemm_fused_kernel(const float* __restrict__ A,
                                  const float* __restrict__ B,
                                  float* __restrict__ C, int M, int K,
                                  const float* __restrict__ dnorm,
                                  const float* __restrict__ bias,
                                  const float* __restrict__ av,
                                  const float* __restrict__ bv,
                                  float* __restrict__ as_out,
                                  float* __restrict__ ad_out) {
    // A tile stored duplicated: As[k][r] = (a, a) for single-LDS.64 broadcast
    __shared__ u64  As[BK][BM + 1];
    __shared__ float Bs[BK][BN];
    const int tx = threadIdx.x, ty = threadIdx.y;
    constexpr int TG = BN / TN;            // threads per row group
    const int tid = ty * TG + tx;
    constexpr int NT = TG * (BM / TM);     // threads per block
    const int rowBase = blockIdx.x * BM;

    u64 acc[TM][TN / 2];
#pragma unroll
    for (int i = 0; i < TM; i++)
#pragma unroll
        for (int j = 0; j < TN / 2; j++) acc[i][j] = 0ull;

    for (int k0 = 0; k0 < K; k0 += BK) {
        // load A tile (BM x BK) as float4, transform, store duplicated
#pragma unroll
        for (int it = tid; it < BM * BK / 4; it += NT) {
            int r = (it * 4) / BK, c = (it * 4) % BK;
            int gr = rowBase + r;
            float4 v = make_float4(0.f, 0.f, 0.f, 0.f);
            if (gr < M) {
                v = *(const float4*)(A + (size_t)gr * K + k0 + c);
                if (TRANSFORM) {
                    float inv = 1.f / dnorm[gr];
                    v.x = fmaxf(v.x * inv + bias[k0 + c + 0], 0.f);
                    v.y = fmaxf(v.y * inv + bias[k0 + c + 1], 0.f);
                    v.z = fmaxf(v.z * inv + bias[k0 + c + 2], 0.f);
                    v.w = fmaxf(v.w * inv + bias[k0 + c + 3], 0.f);
                }
            }
            As[c + 0][r] = pack2(v.x, v.x);
            As[c + 1][r] = pack2(v.y, v.y);
            As[c + 2][r] = pack2(v.z, v.z);
            As[c + 3][r] = pack2(v.w, v.w);
        }
        // load B tile (BK x BN)
#pragma unroll
        for (int it = tid; it < BK * BN / 4; it += NT) {
            int r = (it * 4) / BN, c = (it * 4) % BN;
            *(float4*)&Bs[r][c] = *(const float4*)(B + (size_t)(k0 + r) * BN + c);
        }
        __syncthreads();
#pragma unroll
        for (int k = 0; k < BK; k++) {
            u64 ra[TM], rb[TN / 2];
#pragma unroll
            for (int i = 0; i < TM; i++) ra[i] = As[k][ty * TM + i];
#pragma unroll
            for (int j = 0; j < TN / 2; j++)
                rb[j] = *(const u64*)&Bs[k][tx * TN + 2 * j];
#pragma unroll
            for (int i = 0; i < TM; i++)
#pragma unroll
                for (int j = 0; j < TN / 2; j++)
                    acc[i][j] = ffma2(ra[i], rb[j], acc[i][j]);
        }
        __syncthreads();
    }

    // alpha weights for this thread's columns
    float avr[TN], bvr[TN];
    if (ALPHA) {
#pragma unroll
        for (int j = 0; j < TN; j++) {
            avr[j] = av[tx * TN + j];
            bvr[j] = bv[tx * TN + j];
        }
    }

#pragma unroll
    for (int i = 0; i < TM; i++) {
        int gr = rowBase + ty * TM + i;
        float f[TN];
#pragma unroll
        for (int j = 0; j < TN / 2; j++) unpack2(acc[i][j], f[2 * j], f[2 * j + 1]);
        if (gr < M) {
            *(float4*)(C + (size_t)gr * BN + tx * TN) =
                make_float4(f[0], f[1], f[2], f[3]);
            *(float4*)(C + (size_t)gr * BN + tx * TN + 4) =
                make_float4(f[4], f[5], f[6], f[7]);
        }
        if (ALPHA) {
            float s = 0.f, d = 0.f;
#pragma unroll
            for (int j = 0; j < TN; j++) {
                s += f[j] * avr[j];
                d += f[j] * bvr[j];
            }
#pragma unroll
            for (int off = TG / 2; off > 0; off >>= 1) {
                s += __shfl_xor_sync(0xffffffffu, s, off);
                d += __shfl_xor_sync(0xffffffffu, d, off);
            }
            if (tx == 0 && gr < M) {
                as_out[gr] = s;
                ad_out[gr] = d;
            }
        }
    }
}

// ---------------- fused edge pass: w=exp(leakyrelu(e)); den += w; agg += w*h[s]
template <int H>
__global__ void edge_fused_kernel(const int* __restrict__ ei, int E, int nE,
                                  const float* __restrict__ as,
                                  const float* __restrict__ ad,
                                  const float* __restrict__ h,
                                  float* __restrict__ den,
                                  float* __restrict__ agg) {
    constexpr int G = H / 4;  // threads per edge, one float4 each
    int t = blockIdx.x * blockDim.x + threadIdx.x;
    int e = t / G;
    int lane = t % G;
    if (e >= nE) return;
    int s, d;
    if (e < E) { s = __ldg(&ei[e]); d = __ldg(&ei[E + e]); } else { s = d = e - E; }
    float v = __ldg(&as[s]) + __ldg(&ad[d]);
    v = (v > 0.f) ? v : 0.2f * v;
    float w = __expf(v);
    if (lane == 0) atomicAdd(&den[d], w);
    float4 hv = __ldg(&((const float4*)(h + (size_t)s * H))[lane]);
    float4 o = make_float4(hv.x * w, hv.y * w, hv.z * w, hv.w * w);
    float* p = agg + (size_t)d * H + lane * 4;
    asm volatile("red.global.add.v4.f32 [%0], {%1, %2, %3, %4};" ::"l"(p),
                 "f"(o.x), "f"(o.y), "f"(o.z), "f"(o.w)
                 : "memory");
}

// ---------------- final head: fold layer2 norm+bias+relu, dot with Wfc -----
__global__ void final_kernel(const float* __restrict__ x2,
                             const float* __restrict__ den,
                             const float* __restrict__ b2,
                             const float* __restrict__ Wfc,
                             const float* __restrict__ bfc,
                             float* __restrict__ out, int n) {
    int i = blockIdx.x * blockDim.x + threadIdx.x;
    if (i >= n) return;
    float inv = 1.f / den[i];
    const float4* hp = (const float4*)(x2 + (size_t)i * 32);
    float s = 0.f;
#pragma unroll
    for (int j = 0; j < 8; j++) {
        float4 a = hp[j];
        float4 b = ((const float4*)b2)[j];
        float4 w = ((const float4*)Wfc)[j];
        s += fmaxf(a.x * inv + b.x, 0.f) * w.x;
        s += fmaxf(a.y * inv + b.y, 0.f) * w.y;
        s += fmaxf(a.z * inv + b.z, 0.f) * w.z;
        s += fmaxf(a.w * inv + b.w, 0.f) * w.w;
    }
    out[i] = s + bfc[0];
}

// ---------------- launch ----------------
extern "C" void kernel_launch(void* const* d_in, const int* in_sizes, int n_in,
                              void* d_out, int out_size) {
    const float* x   = (const float*)d_in[0];
    const int*   ei  = (const int*)d_in[1];
    const float* W1  = (const float*)d_in[2];
    const float* as1 = (const float*)d_in[3];
    const float* ad1 = (const float*)d_in[4];
    const float* b1  = (const float*)d_in[5];
    const float* W2  = (const float*)d_in[6];
    const float* as2 = (const float*)d_in[7];
    const float* ad2 = (const float*)d_in[8];
    const float* b2  = (const float*)d_in[9];
    const float* Wfc = (const float*)d_in[10];
    const float* bfc = (const float*)d_in[11];
    float* out = (float*)d_out;

    const int N  = in_sizes[0] / 256;  // 100000
    const int E  = in_sizes[1] / 2;    // 1600000
    const int ET = E + N;              // with self loops

    float *h1, *x1, *h2, *x2, *asb, *adb, *den;
    cudaGetSymbolAddress((void**)&h1, g_h1);
    cudaGetSymbolAddress((void**)&x1, g_x1);
    cudaGetSymbolAddress((void**)&h2, g_h2);
    cudaGetSymbolAddress((void**)&x2, g_x2);
    cudaGetSymbolAddress((void**)&asb, g_as);
    cudaGetSymbolAddress((void**)&adb, g_ad);
    cudaGetSymbolAddress((void**)&den, g_den);

    const int T = 256;
    auto nb = [](long long n, int t) { return (int)((n + t - 1) / t); };
    const int gblk = nb(N, 128);

    // ---------- layer 1 (H=64) ----------
    // gemm1: h1 = x @ W1, epilogue computes as/ad
    gemm_fused_kernel<128, 64, 16, 8, 8, false, true>
        <<<gblk, dim3(8, 16)>>>(x, W1, h1, N, 256, nullptr, nullptr,
                                as1, ad1, asb, adb);
    cudaMemsetAsync(den, 0, (size_t)N * sizeof(float));
    cudaMemsetAsync(x1, 0, (size_t)N * 64 * sizeof(float));
    edge_fused_kernel<64>
        <<<nb((long long)ET * 16, T), T>>>(ei, E, ET, asb, adb, h1, den, x1);

    // ---------- layer 2 (H=32) ----------
    // gemm2: h2 = relu(x1/den + b1) @ W2, epilogue computes as/ad
    gemm_fused_kernel<128, 32, 16, 8, 8, true, true>
        <<<gblk, dim3(4, 16)>>>(x1, W2, h2, N, 64, den, b1,
                                as2, ad2, asb, adb);
    cudaMemsetAsync(den, 0, (size_t)N * sizeof(float));
    cudaMemsetAsync(x2, 0, (size_t)N * 32 * sizeof(float));
    edge_fused_kernel<32>
        <<<nb((long long)ET * 8, T), T>>>(ei, E, ET, asb, adb, h2, den, x2);

    // ---------- head (folds layer2 norm+bias+relu) ----------
    final_kernel<<<nb(N, T), T>>>(x2, den, b2, Wfc, bfc, out, N);
}

// round 4
// speedup vs baseline: 1.4769x; 1.2485x over previous
#include <cuda_runtime.h>

#define NN 100000
#define EMAXC 1700000

// ---------------- scratch (static device globals; no allocs) ----------------
__device__ float g_h1[NN * 64];   // layer1 pre-attention features
__device__ float g_x1[NN * 64];   // layer1 output (normalized+bias+relu)
__device__ float g_h2[NN * 32];   // layer2 pre-attention features
__device__ float g_x2[NN * 32];   // layer2 output (normalized+bias+relu)
__device__ float g_as[NN];
__device__ float g_ad[NN];
__device__ int   g_deg[NN];
__device__ int   g_rowptr[NN + 1];
__device__ int   g_cur[NN];
__device__ int   g_blk[128];
__device__ int   g_esrc[EMAXC];   // CSR: src node of each dst-sorted edge

typedef unsigned long long u64;

__device__ __forceinline__ u64 ffma2(u64 a, u64 b, u64 c) {
    u64 d;
    asm("fma.rn.f32x2 %0, %1, %2, %3;" : "=l"(d) : "l"(a), "l"(b), "l"(c));
    return d;
}
__device__ __forceinline__ u64 pack2(float x, float y) {
    u64 r;
    asm("mov.b64 %0, {%1,%2};" : "=l"(r) : "f"(x), "f"(y));
    return r;
}
__device__ __forceinline__ void unpack2(u64 v, float& x, float& y) {
    asm("mov.b64 {%0,%1}, %2;" : "=f"(x), "=f"(y) : "l"(v));
}

// ======================= CSR build =======================
__global__ void hist_kernel(const int* __restrict__ ei, int E, int nE,
                            int* __restrict__ deg) {
    int e = blockIdx.x * blockDim.x + threadIdx.x;
    if (e >= nE) return;
    int d = (e < E) ? __ldg(&ei[E + e]) : e - E;
    atomicAdd(&deg[d], 1);
}

// block-level inclusive scan of deg -> rowptr[i+1]; block totals to blk[]
__global__ void scan_block_kernel(const int* __restrict__ deg,
                                  int* __restrict__ rowptr,
                                  int* __restrict__ blk, int n) {
    __shared__ int sh[1024];
    int i = blockIdx.x * 1024 + threadIdx.x;
    int v = (i < n) ? deg[i] : 0;
    sh[threadIdx.x] = v;
    __syncthreads();
#pragma unroll
    for (int off = 1; off < 1024; off <<= 1) {
        int t = (threadIdx.x >= off) ? sh[threadIdx.x - off] : 0;
        __syncthreads();
        sh[threadIdx.x] += t;
        __syncthreads();
    }
    if (i < n) rowptr[i + 1] = sh[threadIdx.x];
    if (threadIdx.x == 1023) blk[blockIdx.x] = sh[1023];
}

// exclusive scan of the (<=128) block totals, in place
__global__ void scan_tops_kernel(int* __restrict__ blk, int nb) {
    __shared__ int sh[128];
    int v = (threadIdx.x < nb) ? blk[threadIdx.x] : 0;
    sh[threadIdx.x] = v;
    __syncthreads();
#pragma unroll
    for (int off = 1; off < 128; off <<= 1) {
        int t = (threadIdx.x >= off) ? sh[threadIdx.x - off] : 0;
        __syncthreads();
        sh[threadIdx.x] += t;
        __syncthreads();
    }
    if (threadIdx.x < nb)
        blk[threadIdx.x] = (threadIdx.x == 0) ? 0 : sh[threadIdx.x - 1];
}

// add block offsets; produce cursor (= exclusive start) from inclusive - deg
__global__ void scan_add_kernel(int* __restrict__ rowptr,
                                const int* __restrict__ blk,
                                const int* __restrict__ deg,
                                int* __restrict__ cur, int n) {
    int i = blockIdx.x * 1024 + threadIdx.x;
    if (i >= n) return;
    int v = rowptr[i + 1] + blk[i / 1024];  // final inclusive sum
    rowptr[i + 1] = v;
    cur[i] = v - deg[i];  // start offset of node i
    if (i == 0) rowptr[0] = 0;
}

__global__ void scatter_kernel(const int* __restrict__ ei, int E, int nE,
                               int* __restrict__ cur, int* __restrict__ esrc) {
    int e = blockIdx.x * blockDim.x + threadIdx.x;
    if (e >= nE) return;
    int s, d;
    if (e < E) { s = __ldg(&ei[e]); d = __ldg(&ei[E + e]); } else { s = d = e - E; }
    int p = atomicAdd(&cur[d], 1);
    esrc[p] = s;
}

// ---------------- fused GEMM: C[M,BN] = A[M,K] @ B[K,BN] -------------------
// alpha epilogue: as_out[r] = C[r,:].av ; ad_out[r] = C[r,:].bv
// BN == N exactly. TN == 8. blockDim = (BN/TN, BM/TM)
template <int BM, int BN, int BK, int TM, int TN>
__global__ void gemm_fused_kernel(const float* __restrict__ A,
                                  const float* __restrict__ B,
                                  float* __restrict__ C, int M, int K,
                                  const float* __restrict__ av,
                                  const float* __restrict__ bv,
                                  float* __restrict__ as_out,
                                  float* __restrict__ ad_out) {
    __shared__ u64  As[BK][BM + 1];
    __shared__ float Bs[BK][BN];
    const int tx = threadIdx.x, ty = threadIdx.y;
    constexpr int TG = BN / TN;
    const int tid = ty * TG + tx;
    constexpr int NT = TG * (BM / TM);
    const int rowBase = blockIdx.x * BM;

    u64 acc[TM][TN / 2];
#pragma unroll
    for (int i = 0; i < TM; i++)
#pragma unroll
        for (int j = 0; j < TN / 2; j++) acc[i][j] = 0ull;

    for (int k0 = 0; k0 < K; k0 += BK) {
#pragma unroll
        for (int it = tid; it < BM * BK / 4; it += NT) {
            int r = (it * 4) / BK, c = (it * 4) % BK;
            int gr = rowBase + r;
            float4 v = make_float4(0.f, 0.f, 0.f, 0.f);
            if (gr < M) v = *(const float4*)(A + (size_t)gr * K + k0 + c);
            As[c + 0][r] = pack2(v.x, v.x);
            As[c + 1][r] = pack2(v.y, v.y);
            As[c + 2][r] = pack2(v.z, v.z);
            As[c + 3][r] = pack2(v.w, v.w);
        }
#pragma unroll
        for (int it = tid; it < BK * BN / 4; it += NT) {
            int r = (it * 4) / BN, c = (it * 4) % BN;
            *(float4*)&Bs[r][c] = *(const float4*)(B + (size_t)(k0 + r) * BN + c);
        }
        __syncthreads();
#pragma unroll
        for (int k = 0; k < BK; k++) {
            u64 ra[TM], rb[TN / 2];
#pragma unroll
            for (int i = 0; i < TM; i++) ra[i] = As[k][ty * TM + i];
#pragma unroll
            for (int j = 0; j < TN / 2; j++)
                rb[j] = *(const u64*)&Bs[k][tx * TN + 2 * j];
#pragma unroll
            for (int i = 0; i < TM; i++)
#pragma unroll
                for (int j = 0; j < TN / 2; j++)
                    acc[i][j] = ffma2(ra[i], rb[j], acc[i][j]);
        }
        __syncthreads();
    }

    float avr[TN], bvr[TN];
#pragma unroll
    for (int j = 0; j < TN; j++) {
        avr[j] = av[tx * TN + j];
        bvr[j] = bv[tx * TN + j];
    }

#pragma unroll
    for (int i = 0; i < TM; i++) {
        int gr = rowBase + ty * TM + i;
        float f[TN];
#pragma unroll
        for (int j = 0; j < TN / 2; j++) unpack2(acc[i][j], f[2 * j], f[2 * j + 1]);
        if (gr < M) {
            *(float4*)(C + (size_t)gr * BN + tx * TN) =
                make_float4(f[0], f[1], f[2], f[3]);
            *(float4*)(C + (size_t)gr * BN + tx * TN + 4) =
                make_float4(f[4], f[5], f[6], f[7]);
        }
        float s = 0.f, d = 0.f;
#pragma unroll
        for (int j = 0; j < TN; j++) {
            s += f[j] * avr[j];
            d += f[j] * bvr[j];
        }
#pragma unroll
        for (int off = TG / 2; off > 0; off >>= 1) {
            s += __shfl_xor_sync(0xffffffffu, s, off);
            d += __shfl_xor_sync(0xffffffffu, d, off);
        }
        if (tx == 0 && gr < M) {
            as_out[gr] = s;
            ad_out[gr] = d;
        }
    }
}

// ======== CSR gather aggregation: one warp per node, fused norm+bias+relu ===
template <int H>
__global__ void agg_csr_kernel(const int* __restrict__ rowptr,
                               const int* __restrict__ esrc,
                               const float* __restrict__ as,
                               const float* __restrict__ ad,
                               const float* __restrict__ h,
                               const float* __restrict__ bias,
                               float* __restrict__ out, int n) {
    constexpr int G = H / 4;        // lanes per edge (float4 each)
    constexpr int EPW = 32 / G;     // edges in flight per warp
    int warp = (blockIdx.x * blockDim.x + threadIdx.x) >> 5;
    if (warp >= n) return;
    int lane = threadIdx.x & 31;
    int eslot = lane / G;
    int part = lane % G;

    int beg = __ldg(&rowptr[warp]);
    int end = __ldg(&rowptr[warp + 1]);
    float add = __ldg(&ad[warp]);

    float4 acc = make_float4(0.f, 0.f, 0.f, 0.f);
    float den = 0.f;
    for (int i = beg + eslot; i < end; i += EPW) {
        int s = __ldg(&esrc[i]);
        float v = __ldg(&as[s]) + add;
        v = (v > 0.f) ? v : 0.2f * v;
        float w = __expf(v);
        float4 hv = __ldg(&((const float4*)(h + (size_t)s * H))[part]);
        acc.x += w * hv.x; acc.y += w * hv.y;
        acc.z += w * hv.z; acc.w += w * hv.w;
        den += w;
    }
    // reduce across edge slots (same part, different eslot)
#pragma unroll
    for (int off = G; off < 32; off <<= 1) {
        acc.x += __shfl_xor_sync(0xffffffffu, acc.x, off);
        acc.y += __shfl_xor_sync(0xffffffffu, acc.y, off);
        acc.z += __shfl_xor_sync(0xffffffffu, acc.z, off);
        acc.w += __shfl_xor_sync(0xffffffffu, acc.w, off);
        den   += __shfl_xor_sync(0xffffffffu, den, off);
    }
    if (eslot == 0) {
        float inv = 1.f / den;
        float4 b = __ldg(&((const float4*)bias)[part]);
        float4 o;
        o.x = fmaxf(acc.x * inv + b.x, 0.f);
        o.y = fmaxf(acc.y * inv + b.y, 0.f);
        o.z = fmaxf(acc.z * inv + b.z, 0.f);
        o.w = fmaxf(acc.w * inv + b.w, 0.f);
        ((float4*)(out + (size_t)warp * H))[part] = o;
    }
}

// ---------------- final head: x2 already normalized+bias+relu'd ------------
__global__ void final_kernel(const float* __restrict__ x2,
                             const float* __restrict__ Wfc,
                             const float* __restrict__ bfc,
                             float* __restrict__ out, int n) {
    int i = blockIdx.x * blockDim.x + threadIdx.x;
    if (i >= n) return;
    const float4* hp = (const float4*)(x2 + (size_t)i * 32);
    float s = 0.f;
#pragma unroll
    for (int j = 0; j < 8; j++) {
        float4 a = hp[j];
        float4 w = ((const float4*)Wfc)[j];
        s += a.x * w.x + a.y * w.y + a.z * w.z + a.w * w.w;
    }
    out[i] = s + bfc[0];
}

// ---------------- launch ----------------
extern "C" void kernel_launch(void* const* d_in, const int* in_sizes, int n_in,
                              void* d_out, int out_size) {
    const float* x   = (const float*)d_in[0];
    const int*   ei  = (const int*)d_in[1];
    const float* W1  = (const float*)d_in[2];
    const float* as1 = (const float*)d_in[3];
    const float* ad1 = (const float*)d_in[4];
    const float* b1  = (const float*)d_in[5];
    const float* W2  = (const float*)d_in[6];
    const float* as2 = (const float*)d_in[7];
    const float* ad2 = (const float*)d_in[8];
    const float* b2  = (const float*)d_in[9];
    const float* Wfc = (const float*)d_in[10];
    const float* bfc = (const float*)d_in[11];
    float* out = (float*)d_out;

    const int N  = in_sizes[0] / 256;  // 100000
    const int E  = in_sizes[1] / 2;    // 1600000
    const int ET = E + N;              // with self loops

    float *h1, *x1, *h2, *x2, *asb, *adb;
    int *deg, *rowptr, *cur, *blk, *esrc;
    cudaGetSymbolAddress((void**)&h1, g_h1);
    cudaGetSymbolAddress((void**)&x1, g_x1);
    cudaGetSymbolAddress((void**)&h2, g_h2);
    cudaGetSymbolAddress((void**)&x2, g_x2);
    cudaGetSymbolAddress((void**)&asb, g_as);
    cudaGetSymbolAddress((void**)&adb, g_ad);
    cudaGetSymbolAddress((void**)&deg, g_deg);
    cudaGetSymbolAddress((void**)&rowptr, g_rowptr);
    cudaGetSymbolAddress((void**)&cur, g_cur);
    cudaGetSymbolAddress((void**)&blk, g_blk);
    cudaGetSymbolAddress((void**)&esrc, g_esrc);

    const int T = 256;
    auto nb = [](long long n, int t) { return (int)((n + t - 1) / t); };
    const int nScanBlk = nb(N, 1024);

    // ---------- CSR build ----------
    cudaMemsetAsync(deg, 0, (size_t)N * sizeof(int));
    hist_kernel<<<nb(ET, T), T>>>(ei, E, ET, deg);
    scan_block_kernel<<<nScanBlk, 1024>>>(deg, rowptr, blk, N);
    scan_tops_kernel<<<1, 128>>>(blk, nScanBlk);
    scan_add_kernel<<<nScanBlk, 1024>>>(rowptr, blk, deg, cur, N);
    scatter_kernel<<<nb(ET, T), T>>>(ei, E, ET, cur, esrc);

    // ---------- layer 1 (H=64) ----------
    gemm_fused_kernel<128, 64, 16, 8, 8>
        <<<nb(N, 128), dim3(8, 16)>>>(x, W1, h1, N, 256, as1, ad1, asb, adb);
    agg_csr_kernel<64>
        <<<nb((long long)N * 32, T), T>>>(rowptr, esrc, asb, adb, h1, b1, x1, N);

    // ---------- layer 2 (H=32) ----------
    gemm_fused_kernel<128, 32, 16, 8, 8>
        <<<nb(N, 128), dim3(4, 16)>>>(x1, W2, h2, N, 64, as2, ad2, asb, adb);
    agg_csr_kernel<32>
        <<<nb((long long)N * 32, T), T>>>(rowptr, esrc, asb, adb, h2, b2, x2, N);

    // ---------- head ----------
    final_kernel<<<nb(N, T), T>>>(x2, Wfc, bfc, out, N);
}

// round 5
// speedup vs baseline: 1.4915x; 1.0099x over previous
#include <cuda_runtime.h>

#define NN 100000
#define EMAXC 1700000

// ---------------- scratch (static device globals; no allocs) ----------------
__device__ float g_h1[NN * 64];
__device__ float g_x1[NN * 64];
__device__ float g_h2[NN * 32];
__device__ float g_x2[NN * 32];
__device__ float g_as[NN];
__device__ float g_ad[NN];
__device__ int   g_deg[NN];
__device__ int   g_rowptr[NN + 1];
__device__ int   g_cur[NN];
__device__ int   g_blk[128];
__device__ int   g_esrc[EMAXC];

typedef unsigned long long u64;

__device__ __forceinline__ u64 ffma2(u64 a, u64 b, u64 c) {
    u64 d;
    asm("fma.rn.f32x2 %0, %1, %2, %3;" : "=l"(d) : "l"(a), "l"(b), "l"(c));
    return d;
}
__device__ __forceinline__ u64 pack2(float x, float y) {
    u64 r;
    asm("mov.b64 %0, {%1,%2};" : "=l"(r) : "f"(x), "f"(y));
    return r;
}
__device__ __forceinline__ void unpack2(u64 v, float& x, float& y) {
    asm("mov.b64 {%0,%1}, %2;" : "=f"(x), "=f"(y) : "l"(v));
}

// ======================= CSR build =======================
__global__ void hist_kernel(const int* __restrict__ ei, int E, int nE,
                            int* __restrict__ deg) {
    int e = blockIdx.x * blockDim.x + threadIdx.x;
    if (e >= nE) return;
    int d = (e < E) ? __ldg(&ei[E + e]) : e - E;
    atomicAdd(&deg[d], 1);
}

__global__ void scan_block_kernel(const int* __restrict__ deg,
                                  int* __restrict__ rowptr,
                                  int* __restrict__ blk, int n) {
    __shared__ int sh[1024];
    int i = blockIdx.x * 1024 + threadIdx.x;
    int v = (i < n) ? deg[i] : 0;
    sh[threadIdx.x] = v;
    __syncthreads();
#pragma unroll
    for (int off = 1; off < 1024; off <<= 1) {
        int t = (threadIdx.x >= off) ? sh[threadIdx.x - off] : 0;
        __syncthreads();
        sh[threadIdx.x] += t;
        __syncthreads();
    }
    if (i < n) rowptr[i + 1] = sh[threadIdx.x];
    if (threadIdx.x == 1023) blk[blockIdx.x] = sh[1023];
}

__global__ void scan_tops_kernel(int* __restrict__ blk, int nb) {
    __shared__ int sh[128];
    int v = (threadIdx.x < nb) ? blk[threadIdx.x] : 0;
    sh[threadIdx.x] = v;
    __syncthreads();
#pragma unroll
    for (int off = 1; off < 128; off <<= 1) {
        int t = (threadIdx.x >= off) ? sh[threadIdx.x - off] : 0;
        __syncthreads();
        sh[threadIdx.x] += t;
        __syncthreads();
    }
    if (threadIdx.x < nb)
        blk[threadIdx.x] = (threadIdx.x == 0) ? 0 : sh[threadIdx.x - 1];
}

__global__ void scan_add_kernel(int* __restrict__ rowptr,
                                const int* __restrict__ blk,
                                const int* __restrict__ deg,
                                int* __restrict__ cur, int n) {
    int i = blockIdx.x * 1024 + threadIdx.x;
    if (i >= n) return;
    int v = rowptr[i + 1] + blk[i / 1024];
    rowptr[i + 1] = v;
    cur[i] = v - deg[i];
    if (i == 0) rowptr[0] = 0;
}

__global__ void scatter_kernel(const int* __restrict__ ei, int E, int nE,
                               int* __restrict__ cur, int* __restrict__ esrc) {
    int e = blockIdx.x * blockDim.x + threadIdx.x;
    if (e >= nE) return;
    int s, d;
    if (e < E) { s = __ldg(&ei[e]); d = __ldg(&ei[E + e]); } else { s = d = e - E; }
    int p = atomicAdd(&cur[d], 1);
    esrc[p] = s;
}

// ---------------- fused GEMM: C[M,BN] = A[M,K] @ B[K,BN] -------------------
// alpha epilogue: as_out[r] = C[r,:].av ; ad_out[r] = C[r,:].bv
// BN == N exactly. TN == 8. blockDim = (BN/TN, BM/TM)
template <int BM, int BN, int BK, int TM, int TN>
__global__ void gemm_fused_kernel(const float* __restrict__ A,
                                  const float* __restrict__ B,
                                  float* __restrict__ C, int M, int K,
                                  const float* __restrict__ av,
                                  const float* __restrict__ bv,
                                  float* __restrict__ as_out,
                                  float* __restrict__ ad_out) {
    __shared__ u64  As[BK][BM + 1];
    __shared__ float Bs[BK][BN];
    const int tx = threadIdx.x, ty = threadIdx.y;
    constexpr int TG = BN / TN;
    const int tid = ty * TG + tx;
    constexpr int NT = TG * (BM / TM);
    const int rowBase = blockIdx.x * BM;

    u64 acc[TM][TN / 2];
#pragma unroll
    for (int i = 0; i < TM; i++)
#pragma unroll
        for (int j = 0; j < TN / 2; j++) acc[i][j] = 0ull;

    for (int k0 = 0; k0 < K; k0 += BK) {
#pragma unroll
        for (int it = tid; it < BM * BK / 4; it += NT) {
            int r = (it * 4) / BK, c = (it * 4) % BK;
            int gr = rowBase + r;
            float4 v = make_float4(0.f, 0.f, 0.f, 0.f);
            if (gr < M) v = *(const float4*)(A + (size_t)gr * K + k0 + c);
            As[c + 0][r] = pack2(v.x, v.x);
            As[c + 1][r] = pack2(v.y, v.y);
            As[c + 2][r] = pack2(v.z, v.z);
            As[c + 3][r] = pack2(v.w, v.w);
        }
#pragma unroll
        for (int it = tid; it < BK * BN / 4; it += NT) {
            int r = (it * 4) / BN, c = (it * 4) % BN;
            *(float4*)&Bs[r][c] = *(const float4*)(B + (size_t)(k0 + r) * BN + c);
        }
        __syncthreads();
#pragma unroll
        for (int k = 0; k < BK; k++) {
            u64 ra[TM], rb[TN / 2];
#pragma unroll
            for (int i = 0; i < TM; i++) ra[i] = As[k][ty * TM + i];
#pragma unroll
            for (int j = 0; j < TN / 2; j++)
                rb[j] = *(const u64*)&Bs[k][tx * TN + 2 * j];
#pragma unroll
            for (int i = 0; i < TM; i++)
#pragma unroll
                for (int j = 0; j < TN / 2; j++)
                    acc[i][j] = ffma2(ra[i], rb[j], acc[i][j]);
        }
        __syncthreads();
    }

    float avr[TN], bvr[TN];
#pragma unroll
    for (int j = 0; j < TN; j++) {
        avr[j] = av[tx * TN + j];
        bvr[j] = bv[tx * TN + j];
    }

#pragma unroll
    for (int i = 0; i < TM; i++) {
        int gr = rowBase + ty * TM + i;
        float f[TN];
#pragma unroll
        for (int j = 0; j < TN / 2; j++) unpack2(acc[i][j], f[2 * j], f[2 * j + 1]);
        if (gr < M) {
            *(float4*)(C + (size_t)gr * BN + tx * TN) =
                make_float4(f[0], f[1], f[2], f[3]);
            *(float4*)(C + (size_t)gr * BN + tx * TN + 4) =
                make_float4(f[4], f[5], f[6], f[7]);
        }
        float s = 0.f, d = 0.f;
#pragma unroll
        for (int j = 0; j < TN; j++) {
            s += f[j] * avr[j];
            d += f[j] * bvr[j];
        }
#pragma unroll
        for (int off = TG / 2; off > 0; off >>= 1) {
            s += __shfl_xor_sync(0xffffffffu, s, off);
            d += __shfl_xor_sync(0xffffffffu, d, off);
        }
        if (tx == 0 && gr < M) {
            as_out[gr] = s;
            ad_out[gr] = d;
        }
    }
}

// ======== CSR gather aggregation: one warp per node, fused norm+bias+relu ===
template <int H>
__global__ void agg_csr_kernel(const int* __restrict__ rowptr,
                               const int* __restrict__ esrc,
                               const float* __restrict__ as,
                               const float* __restrict__ ad,
                               const float* __restrict__ h,
                               const float* __restrict__ bias,
                               float* __restrict__ out, int n) {
    constexpr int G = H / 4;
    constexpr int EPW = 32 / G;
    int warp = (blockIdx.x * blockDim.x + threadIdx.x) >> 5;
    if (warp >= n) return;
    int lane = threadIdx.x & 31;
    int eslot = lane / G;
    int part = lane % G;

    int beg = __ldg(&rowptr[warp]);
    int end = __ldg(&rowptr[warp + 1]);
    float add = __ldg(&ad[warp]);

    float4 acc = make_float4(0.f, 0.f, 0.f, 0.f);
    float den = 0.f;
    for (int i = beg + eslot; i < end; i += EPW) {
        int s = __ldg(&esrc[i]);
        float v = __ldg(&as[s]) + add;
        v = (v > 0.f) ? v : 0.2f * v;
        float w = __expf(v);
        float4 hv = __ldg(&((const float4*)(h + (size_t)s * H))[part]);
        acc.x += w * hv.x; acc.y += w * hv.y;
        acc.z += w * hv.z; acc.w += w * hv.w;
        den += w;
    }
#pragma unroll
    for (int off = G; off < 32; off <<= 1) {
        acc.x += __shfl_xor_sync(0xffffffffu, acc.x, off);
        acc.y += __shfl_xor_sync(0xffffffffu, acc.y, off);
        acc.z += __shfl_xor_sync(0xffffffffu, acc.z, off);
        acc.w += __shfl_xor_sync(0xffffffffu, acc.w, off);
        den   += __shfl_xor_sync(0xffffffffu, den, off);
    }
    if (eslot == 0) {
        float inv = 1.f / den;
        float4 b = __ldg(&((const float4*)bias)[part]);
        float4 o;
        o.x = fmaxf(acc.x * inv + b.x, 0.f);
        o.y = fmaxf(acc.y * inv + b.y, 0.f);
        o.z = fmaxf(acc.z * inv + b.z, 0.f);
        o.w = fmaxf(acc.w * inv + b.w, 0.f);
        ((float4*)(out + (size_t)warp * H))[part] = o;
    }
}

// ---------------- final head ----------------
__global__ void final_kernel(const float* __restrict__ x2,
                             const float* __restrict__ Wfc,
                             const float* __restrict__ bfc,
                             float* __restrict__ out, int n) {
    int i = blockIdx.x * blockDim.x + threadIdx.x;
    if (i >= n) return;
    const float4* hp = (const float4*)(x2 + (size_t)i * 32);
    float s = 0.f;
#pragma unroll
    for (int j = 0; j < 8; j++) {
        float4 a = hp[j];
        float4 w = ((const float4*)Wfc)[j];
        s += a.x * w.x + a.y * w.y + a.z * w.z + a.w * w.w;
    }
    out[i] = s + bfc[0];
}

// ---------------- launch ----------------
extern "C" void kernel_launch(void* const* d_in, const int* in_sizes, int n_in,
                              void* d_out, int out_size) {
    const float* x   = (const float*)d_in[0];
    const int*   ei  = (const int*)d_in[1];
    const float* W1  = (const float*)d_in[2];
    const float* as1 = (const float*)d_in[3];
    const float* ad1 = (const float*)d_in[4];
    const float* b1  = (const float*)d_in[5];
    const float* W2  = (const float*)d_in[6];
    const float* as2 = (const float*)d_in[7];
    const float* ad2 = (const float*)d_in[8];
    const float* b2  = (const float*)d_in[9];
    const float* Wfc = (const float*)d_in[10];
    const float* bfc = (const float*)d_in[11];
    float* out = (float*)d_out;

    const int N  = in_sizes[0] / 256;
    const int E  = in_sizes[1] / 2;
    const int ET = E + N;

    float *h1, *x1, *h2, *x2, *asb, *adb;
    int *deg, *rowptr, *cur, *blk, *esrc;
    cudaGetSymbolAddress((void**)&h1, g_h1);
    cudaGetSymbolAddress((void**)&x1, g_x1);
    cudaGetSymbolAddress((void**)&h2, g_h2);
    cudaGetSymbolAddress((void**)&x2, g_x2);
    cudaGetSymbolAddress((void**)&asb, g_as);
    cudaGetSymbolAddress((void**)&adb, g_ad);
    cudaGetSymbolAddress((void**)&deg, g_deg);
    cudaGetSymbolAddress((void**)&rowptr, g_rowptr);
    cudaGetSymbolAddress((void**)&cur, g_cur);
    cudaGetSymbolAddress((void**)&blk, g_blk);
    cudaGetSymbolAddress((void**)&esrc, g_esrc);

    // side stream + events (created once, outside any capture)
    static cudaStream_t s2 = nullptr;
    static cudaEvent_t evFork = nullptr, evJoin = nullptr;
    if (!s2) {
        cudaStreamCreateWithFlags(&s2, cudaStreamNonBlocking);
        cudaEventCreateWithFlags(&evFork, cudaEventDisableTiming);
        cudaEventCreateWithFlags(&evJoin, cudaEventDisableTiming);
    }

    const int T = 256;
    auto nb = [](long long n, int t) { return (int)((n + t - 1) / t); };
    const int nScanBlk = nb(N, 1024);

    // ---------- fork: CSR build on side stream ----------
    cudaEventRecord(evFork, 0);
    cudaStreamWaitEvent(s2, evFork, 0);
    cudaMemsetAsync(deg, 0, (size_t)N * sizeof(int), s2);
    hist_kernel<<<nb(ET, T), T, 0, s2>>>(ei, E, ET, deg);
    scan_block_kernel<<<nScanBlk, 1024, 0, s2>>>(deg, rowptr, blk, N);
    scan_tops_kernel<<<1, 128, 0, s2>>>(blk, nScanBlk);
    scan_add_kernel<<<nScanBlk, 1024, 0, s2>>>(rowptr, blk, deg, cur, N);
    scatter_kernel<<<nb(ET, T), T, 0, s2>>>(ei, E, ET, cur, esrc);
    cudaEventRecord(evJoin, s2);

    // ---------- main stream: gemm1 in parallel with CSR ----------
    gemm_fused_kernel<128, 64, 32, 8, 8>
        <<<nb(N, 128), dim3(8, 16)>>>(x, W1, h1, N, 256, as1, ad1, asb, adb);

    // ---------- join, then aggregation ----------
    cudaStreamWaitEvent(0, evJoin, 0);
    agg_csr_kernel<64>
        <<<nb((long long)N * 32, T), T>>>(rowptr, esrc, asb, adb, h1, b1, x1, N);

    // ---------- layer 2 (H=32) ----------
    gemm_fused_kernel<128, 32, 32, 4, 8>
        <<<nb(N, 128), dim3(4, 32)>>>(x1, W2, h2, N, 64, as2, ad2, asb, adb);
    agg_csr_kernel<32>
        <<<nb((long long)N * 32, T), T>>>(rowptr, esrc, asb, adb, h2, b2, x2, N);

    // ---------- head ----------
    final_kernel<<<nb(N, T), T>>>(x2, Wfc, bfc, out, N);
}

// round 7
// speedup vs baseline: 1.8023x; 1.2084x over previous
#include <cuda_runtime.h>
#include <cuda_bf16.h>
#include <cstdint>

#define NN 100000
#define EMAXC 1700000

// ---------------- scratch (static device globals; no allocs) ----------------
__device__ float g_h1[NN * 64];
__device__ float g_x1[NN * 64];
__device__ float g_h2[NN * 32];
__device__ float g_x2[NN * 32];
__device__ float g_as[NN];
__device__ float g_ad[NN];
__device__ int   g_deg[NN];
__device__ int   g_rowptr[NN + 1];
__device__ int   g_cur[NN];
__device__ int   g_blk[128];
__device__ int   g_esrc[EMAXC];

typedef unsigned long long u64;

__device__ __forceinline__ u64 ffma2(u64 a, u64 b, u64 c) {
    u64 d;
    asm("fma.rn.f32x2 %0, %1, %2, %3;" : "=l"(d) : "l"(a), "l"(b), "l"(c));
    return d;
}
__device__ __forceinline__ u64 pack2(float x, float y) {
    u64 r;
    asm("mov.b64 %0, {%1,%2};" : "=l"(r) : "f"(x), "f"(y));
    return r;
}
__device__ __forceinline__ void unpack2(u64 v, float& x, float& y) {
    asm("mov.b64 {%0,%1}, %2;" : "=f"(x), "=f"(y) : "l"(v));
}

// ================= gemm1 via mma.sync (bf16 split, f32 accum) ===============
// h1[M,64] = x[M,256] @ W1[256,64], plus alpha epilogue.
// Block: 256 threads (8 warps); each warp owns 16 rows. Full K resident.
// Smem: A hi/lo [128][264] bf16, B^T hi/lo [64][264] bf16 (padded rows).
#define ASTR 264
#define A_HI_OFF 0
#define A_LO_OFF 67584
#define B_HI_OFF 135168
#define B_LO_OFF 168960
#define G1_SMEM  202752

__device__ __forceinline__ void mma16816(float* c, uint32_t a0, uint32_t a1,
                                         uint32_t a2, uint32_t a3,
                                         uint32_t b0, uint32_t b1) {
    asm volatile(
        "mma.sync.aligned.m16n8k16.row.col.f32.bf16.bf16.f32 "
        "{%0,%1,%2,%3}, {%4,%5,%6,%7}, {%8,%9}, {%0,%1,%2,%3};"
        : "+f"(c[0]), "+f"(c[1]), "+f"(c[2]), "+f"(c[3])
        : "r"(a0), "r"(a1), "r"(a2), "r"(a3), "r"(b0), "r"(b1));
}

__global__ void __launch_bounds__(256, 1)
gemm1_mma_kernel(const float* __restrict__ A,    // [M,256]
                 const float* __restrict__ W,    // [256,64]
                 float* __restrict__ C,          // [M,64]
                 int M,
                 const float* __restrict__ av, const float* __restrict__ bv,
                 float* __restrict__ as_out, float* __restrict__ ad_out) {
    extern __shared__ char smem[];
    __nv_bfloat16* Ahi = (__nv_bfloat16*)(smem + A_HI_OFF);
    __nv_bfloat16* Alo = (__nv_bfloat16*)(smem + A_LO_OFF);
    __nv_bfloat16* Bhi = (__nv_bfloat16*)(smem + B_HI_OFF);
    __nv_bfloat16* Blo = (__nv_bfloat16*)(smem + B_LO_OFF);

    const int tid = threadIdx.x;
    const int wid = tid >> 5, lane = tid & 31;
    const int gid = lane >> 2, tig = lane & 3;
    const int rowBase = blockIdx.x * 128;

    // ---- convert A tile: 128x256 fp32 -> bf16 hi/lo ----
    for (int it = tid; it < 128 * 64; it += 256) {
        int r = it >> 6, c4 = (it & 63) << 2;
        int gr = rowBase + r;
        float4 v = make_float4(0.f, 0.f, 0.f, 0.f);
        if (gr < M) v = __ldg((const float4*)(A + (size_t)gr * 256 + c4));
        __nv_bfloat162 h0 = __floats2bfloat162_rn(v.x, v.y);
        __nv_bfloat162 h1 = __floats2bfloat162_rn(v.z, v.w);
        float2 f0 = __bfloat1622float2(h0), f1 = __bfloat1622float2(h1);
        __nv_bfloat162 l0 = __floats2bfloat162_rn(v.x - f0.x, v.y - f0.y);
        __nv_bfloat162 l1 = __floats2bfloat162_rn(v.z - f1.x, v.w - f1.y);
        size_t o = (size_t)r * ASTR + c4;
        *(__nv_bfloat162*)&Ahi[o]     = h0;
        *(__nv_bfloat162*)&Ahi[o + 2] = h1;
        *(__nv_bfloat162*)&Alo[o]     = l0;
        *(__nv_bfloat162*)&Alo[o + 2] = l1;
    }
    // ---- convert B^T: Bt[n][k] = W[k*64+n], bf16 hi/lo ----
    for (int it = tid; it < 64 * 256; it += 256) {
        int n = it & 63, k = it >> 6;
        float w = __ldg(&W[(size_t)k * 64 + n]);
        __nv_bfloat16 hi = __float2bfloat16(w);
        __nv_bfloat16 lo = __float2bfloat16(w - __bfloat162float(hi));
        Bhi[(size_t)n * ASTR + k] = hi;
        Blo[(size_t)n * ASTR + k] = lo;
    }
    __syncthreads();

    // ---- MMA mainloop: 3 passes x 16 ksteps x 8 ntiles ----
    float acc[8][4];
#pragma unroll
    for (int t = 0; t < 8; t++)
#pragma unroll
        for (int j = 0; j < 4; j++) acc[t][j] = 0.f;

    const int arow0 = wid * 16 + gid;
#pragma unroll
    for (int pass = 0; pass < 3; pass++) {
        const __nv_bfloat16* Ap = (pass == 2) ? Alo : Ahi;
        const __nv_bfloat16* Bp = (pass == 1) ? Blo : Bhi;
#pragma unroll 4
        for (int k0 = 0; k0 < 256; k0 += 16) {
            uint32_t a0 = *(const uint32_t*)&Ap[(size_t)arow0 * ASTR + k0 + 2 * tig];
            uint32_t a1 = *(const uint32_t*)&Ap[(size_t)(arow0 + 8) * ASTR + k0 + 2 * tig];
            uint32_t a2 = *(const uint32_t*)&Ap[(size_t)arow0 * ASTR + k0 + 2 * tig + 8];
            uint32_t a3 = *(const uint32_t*)&Ap[(size_t)(arow0 + 8) * ASTR + k0 + 2 * tig + 8];
#pragma unroll
            for (int nt = 0; nt < 8; nt++) {
                uint32_t b0 = *(const uint32_t*)&Bp[(size_t)(nt * 8 + gid) * ASTR + k0 + 2 * tig];
                uint32_t b1 = *(const uint32_t*)&Bp[(size_t)(nt * 8 + gid) * ASTR + k0 + 2 * tig + 8];
                mma16816(acc[nt], a0, a1, a2, a3, b0, b1);
            }
        }
    }

    // ---- epilogue: store C rows + alpha dots ----
    int grLo = rowBase + wid * 16 + gid;
    int grHi = grLo + 8;
    float sLo = 0.f, dLo = 0.f, sHi = 0.f, dHi = 0.f;
#pragma unroll
    for (int nt = 0; nt < 8; nt++) {
        int col = nt * 8 + 2 * tig;
        float a0 = __ldg(&av[col]), a1 = __ldg(&av[col + 1]);
        float b0 = __ldg(&bv[col]), b1 = __ldg(&bv[col + 1]);
        if (grLo < M)
            *(float2*)(C + (size_t)grLo * 64 + col) = make_float2(acc[nt][0], acc[nt][1]);
        if (grHi < M)
            *(float2*)(C + (size_t)grHi * 64 + col) = make_float2(acc[nt][2], acc[nt][3]);
        sLo += acc[nt][0] * a0 + acc[nt][1] * a1;
        dLo += acc[nt][0] * b0 + acc[nt][1] * b1;
        sHi += acc[nt][2] * a0 + acc[nt][3] * a1;
        dHi += acc[nt][2] * b0 + acc[nt][3] * b1;
    }
#pragma unroll
    for (int off = 1; off < 4; off <<= 1) {
        sLo += __shfl_xor_sync(0xffffffffu, sLo, off);
        dLo += __shfl_xor_sync(0xffffffffu, dLo, off);
        sHi += __shfl_xor_sync(0xffffffffu, sHi, off);
        dHi += __shfl_xor_sync(0xffffffffu, dHi, off);
    }
    if (tig == 0) {
        if (grLo < M) { as_out[grLo] = sLo; ad_out[grLo] = dLo; }
        if (grHi < M) { as_out[grHi] = sHi; ad_out[grHi] = dHi; }
    }
}

// ======================= CSR build =======================
__global__ void hist_kernel(const int* __restrict__ ei, int E, int nE,
                            int* __restrict__ deg) {
    int e = blockIdx.x * blockDim.x + threadIdx.x;
    if (e >= nE) return;
    int d = (e < E) ? __ldg(&ei[E + e]) : e - E;
    atomicAdd(&deg[d], 1);
}

__global__ void scan_block_kernel(const int* __restrict__ deg,
                                  int* __restrict__ rowptr,
                                  int* __restrict__ blk, int n) {
    __shared__ int sh[1024];
    int i = blockIdx.x * 1024 + threadIdx.x;
    int v = (i < n) ? deg[i] : 0;
    sh[threadIdx.x] = v;
    __syncthreads();
#pragma unroll
    for (int off = 1; off < 1024; off <<= 1) {
        int t = (threadIdx.x >= off) ? sh[threadIdx.x - off] : 0;
        __syncthreads();
        sh[threadIdx.x] += t;
        __syncthreads();
    }
    if (i < n) rowptr[i + 1] = sh[threadIdx.x];
    if (threadIdx.x == 1023) blk[blockIdx.x] = sh[1023];
}

__global__ void scan_tops_kernel(int* __restrict__ blk, int nb) {
    __shared__ int sh[128];
    int v = (threadIdx.x < nb) ? blk[threadIdx.x] : 0;
    sh[threadIdx.x] = v;
    __syncthreads();
#pragma unroll
    for (int off = 1; off < 128; off <<= 1) {
        int t = (threadIdx.x >= off) ? sh[threadIdx.x - off] : 0;
        __syncthreads();
        sh[threadIdx.x] += t;
        __syncthreads();
    }
    if (threadIdx.x < nb)
        blk[threadIdx.x] = (threadIdx.x == 0) ? 0 : sh[threadIdx.x - 1];
}

__global__ void scan_add_kernel(int* __restrict__ rowptr,
                                const int* __restrict__ blk,
                                const int* __restrict__ deg,
                                int* __restrict__ cur, int n) {
    int i = blockIdx.x * 1024 + threadIdx.x;
    if (i >= n) return;
    int v = rowptr[i + 1] + blk[i / 1024];
    rowptr[i + 1] = v;
    cur[i] = v - deg[i];
    if (i == 0) rowptr[0] = 0;
}

__global__ void scatter_kernel(const int* __restrict__ ei, int E, int nE,
                               int* __restrict__ cur, int* __restrict__ esrc) {
    int e = blockIdx.x * blockDim.x + threadIdx.x;
    if (e >= nE) return;
    int s, d;
    if (e < E) { s = __ldg(&ei[e]); d = __ldg(&ei[E + e]); } else { s = d = e - E; }
    int p = atomicAdd(&cur[d], 1);
    esrc[p] = s;
}

// ---------------- FFMA2 GEMM (layer 2): C[M,BN] = A[M,K] @ B[K,BN] ---------
template <int BM, int BN, int BK, int TM, int TN>
__global__ void gemm_fused_kernel(const float* __restrict__ A,
                                  const float* __restrict__ B,
                                  float* __restrict__ C, int M, int K,
                                  const float* __restrict__ av,
                                  const float* __restrict__ bv,
                                  float* __restrict__ as_out,
                                  float* __restrict__ ad_out) {
    __shared__ u64  As[BK][BM + 1];
    __shared__ float Bs[BK][BN];
    const int tx = threadIdx.x, ty = threadIdx.y;
    constexpr int TG = BN / TN;
    const int tid = ty * TG + tx;
    constexpr int NT = TG * (BM / TM);
    const int rowBase = blockIdx.x * BM;

    u64 acc[TM][TN / 2];
#pragma unroll
    for (int i = 0; i < TM; i++)
#pragma unroll
        for (int j = 0; j < TN / 2; j++) acc[i][j] = 0ull;

    for (int k0 = 0; k0 < K; k0 += BK) {
#pragma unroll
        for (int it = tid; it < BM * BK / 4; it += NT) {
            int r = (it * 4) / BK, c = (it * 4) % BK;
            int gr = rowBase + r;
            float4 v = make_float4(0.f, 0.f, 0.f, 0.f);
            if (gr < M) v = *(const float4*)(A + (size_t)gr * K + k0 + c);
            As[c + 0][r] = pack2(v.x, v.x);
            As[c + 1][r] = pack2(v.y, v.y);
            As[c + 2][r] = pack2(v.z, v.z);
            As[c + 3][r] = pack2(v.w, v.w);
        }
#pragma unroll
        for (int it = tid; it < BK * BN / 4; it += NT) {
            int r = (it * 4) / BN, c = (it * 4) % BN;
            *(float4*)&Bs[r][c] = *(const float4*)(B + (size_t)(k0 + r) * BN + c);
        }
        __syncthreads();
#pragma unroll
        for (int k = 0; k < BK; k++) {
            u64 ra[TM], rb[TN / 2];
#pragma unroll
            for (int i = 0; i < TM; i++) ra[i] = As[k][ty * TM + i];
#pragma unroll
            for (int j = 0; j < TN / 2; j++)
                rb[j] = *(const u64*)&Bs[k][tx * TN + 2 * j];
#pragma unroll
            for (int i = 0; i < TM; i++)
#pragma unroll
                for (int j = 0; j < TN / 2; j++)
                    acc[i][j] = ffma2(ra[i], rb[j], acc[i][j]);
        }
        __syncthreads();
    }

    float avr[TN], bvr[TN];
#pragma unroll
    for (int j = 0; j < TN; j++) {
        avr[j] = av[tx * TN + j];
        bvr[j] = bv[tx * TN + j];
    }

#pragma unroll
    for (int i = 0; i < TM; i++) {
        int gr = rowBase + ty * TM + i;
        float f[TN];
#pragma unroll
        for (int j = 0; j < TN / 2; j++) unpack2(acc[i][j], f[2 * j], f[2 * j + 1]);
        if (gr < M) {
            *(float4*)(C + (size_t)gr * BN + tx * TN) =
                make_float4(f[0], f[1], f[2], f[3]);
            *(float4*)(C + (size_t)gr * BN + tx * TN + 4) =
                make_float4(f[4], f[5], f[6], f[7]);
        }
        float s = 0.f, d = 0.f;
#pragma unroll
        for (int j = 0; j < TN; j++) {
            s += f[j] * avr[j];
            d += f[j] * bvr[j];
        }
#pragma unroll
        for (int off = TG / 2; off > 0; off >>= 1) {
            s += __shfl_xor_sync(0xffffffffu, s, off);
            d += __shfl_xor_sync(0xffffffffu, d, off);
        }
        if (tx == 0 && gr < M) {
            as_out[gr] = s;
            ad_out[gr] = d;
        }
    }
}

// ======== CSR gather aggregation: one warp per node, fused norm+bias+relu ===
template <int H>
__global__ void agg_csr_kernel(const int* __restrict__ rowptr,
                               const int* __restrict__ esrc,
                               const float* __restrict__ as,
                               const float* __restrict__ ad,
                               const float* __restrict__ h,
                               const float* __restrict__ bias,
                               float* __restrict__ out, int n) {
    constexpr int G = H / 4;
    constexpr int EPW = 32 / G;
    int warp = (blockIdx.x * blockDim.x + threadIdx.x) >> 5;
    if (warp >= n) return;
    int lane = threadIdx.x & 31;
    int eslot = lane / G;
    int part = lane % G;

    int beg = __ldg(&rowptr[warp]);
    int end = __ldg(&rowptr[warp + 1]);
    float add = __ldg(&ad[warp]);

    float4 acc = make_float4(0.f, 0.f, 0.f, 0.f);
    float den = 0.f;
    for (int i = beg + eslot; i < end; i += EPW) {
        int s = __ldg(&esrc[i]);
        float v = __ldg(&as[s]) + add;
        v = (v > 0.f) ? v : 0.2f * v;
        float w = __expf(v);
        float4 hv = __ldg(&((const float4*)(h + (size_t)s * H))[part]);
        acc.x += w * hv.x; acc.y += w * hv.y;
        acc.z += w * hv.z; acc.w += w * hv.w;
        den += w;
    }
#pragma unroll
    for (int off = G; off < 32; off <<= 1) {
        acc.x += __shfl_xor_sync(0xffffffffu, acc.x, off);
        acc.y += __shfl_xor_sync(0xffffffffu, acc.y, off);
        acc.z += __shfl_xor_sync(0xffffffffu, acc.z, off);
        acc.w += __shfl_xor_sync(0xffffffffu, acc.w, off);
        den   += __shfl_xor_sync(0xffffffffu, den, off);
    }
    if (eslot == 0) {
        float inv = 1.f / den;
        float4 b = __ldg(&((const float4*)bias)[part]);
        float4 o;
        o.x = fmaxf(acc.x * inv + b.x, 0.f);
        o.y = fmaxf(acc.y * inv + b.y, 0.f);
        o.z = fmaxf(acc.z * inv + b.z, 0.f);
        o.w = fmaxf(acc.w * inv + b.w, 0.f);
        ((float4*)(out + (size_t)warp * H))[part] = o;
    }
}

// ---------------- final head ----------------
__global__ void final_kernel(const float* __restrict__ x2,
                             const float* __restrict__ Wfc,
                             const float* __restrict__ bfc,
                             float* __restrict__ out, int n) {
    int i = blockIdx.x * blockDim.x + threadIdx.x;
    if (i >= n) return;
    const float4* hp = (const float4*)(x2 + (size_t)i * 32);
    float s = 0.f;
#pragma unroll
    for (int j = 0; j < 8; j++) {
        float4 a = hp[j];
        float4 w = ((const float4*)Wfc)[j];
        s += a.x * w.x + a.y * w.y + a.z * w.z + a.w * w.w;
    }
    out[i] = s + bfc[0];
}

// ---------------- launch ----------------
extern "C" void kernel_launch(void* const* d_in, const int* in_sizes, int n_in,
                              void* d_out, int out_size) {
    const float* x   = (const float*)d_in[0];
    const int*   ei  = (const int*)d_in[1];
    const float* W1  = (const float*)d_in[2];
    const float* as1 = (const float*)d_in[3];
    const float* ad1 = (const float*)d_in[4];
    const float* b1  = (const float*)d_in[5];
    const float* W2  = (const float*)d_in[6];
    const float* as2 = (const float*)d_in[7];
    const float* ad2 = (const float*)d_in[8];
    const float* b2  = (const float*)d_in[9];
    const float* Wfc = (const float*)d_in[10];
    const float* bfc = (const float*)d_in[11];
    float* out = (float*)d_out;

    const int N  = in_sizes[0] / 256;
    const int E  = in_sizes[1] / 2;
    const int ET = E + N;

    float *h1, *x1, *h2, *x2, *asb, *adb;
    int *deg, *rowptr, *cur, *blk, *esrc;
    cudaGetSymbolAddress((void**)&h1, g_h1);
    cudaGetSymbolAddress((void**)&x1, g_x1);
    cudaGetSymbolAddress((void**)&h2, g_h2);
    cudaGetSymbolAddress((void**)&x2, g_x2);
    cudaGetSymbolAddress((void**)&asb, g_as);
    cudaGetSymbolAddress((void**)&adb, g_ad);
    cudaGetSymbolAddress((void**)&deg, g_deg);
    cudaGetSymbolAddress((void**)&rowptr, g_rowptr);
    cudaGetSymbolAddress((void**)&cur, g_cur);
    cudaGetSymbolAddress((void**)&blk, g_blk);
    cudaGetSymbolAddress((void**)&esrc, g_esrc);

    static cudaStream_t s2 = nullptr;
    static cudaEvent_t evFork = nullptr, evJoin = nullptr;
    static bool attrSet = false;
    if (!s2) {
        cudaStreamCreateWithFlags(&s2, cudaStreamNonBlocking);
        cudaEventCreateWithFlags(&evFork, cudaEventDisableTiming);
        cudaEventCreateWithFlags(&evJoin, cudaEventDisableTiming);
    }
    if (!attrSet) {
        cudaFuncSetAttribute(gemm1_mma_kernel,
                             cudaFuncAttributeMaxDynamicSharedMemorySize,
                             G1_SMEM);
        attrSet = true;
    }

    const int T = 256;
    auto nb = [](long long n, int t) { return (int)((n + t - 1) / t); };
    const int nScanBlk = nb(N, 1024);

    // ---------- fork: CSR build on side stream ----------
    cudaEventRecord(evFork, 0);
    cudaStreamWaitEvent(s2, evFork, 0);
    cudaMemsetAsync(deg, 0, (size_t)N * sizeof(int), s2);
    hist_kernel<<<nb(ET, T), T, 0, s2>>>(ei, E, ET, deg);               // 1
    scan_block_kernel<<<nScanBlk, 1024, 0, s2>>>(deg, rowptr, blk, N);  // 2
    scan_tops_kernel<<<1, 128, 0, s2>>>(blk, nScanBlk);                 // 3

    // ---------- main stream: mma.sync gemm1 (4th launch -> ncu target) -----
    gemm1_mma_kernel<<<nb(N, 128), 256, G1_SMEM>>>(x, W1, h1, N, as1, ad1,
                                                   asb, adb);           // 4

    scan_add_kernel<<<nScanBlk, 1024, 0, s2>>>(rowptr, blk, deg, cur, N); // 5
    scatter_kernel<<<nb(ET, T), T, 0, s2>>>(ei, E, ET, cur, esrc);      // 6
    cudaEventRecord(evJoin, s2);

    // ---------- join, then aggregation ----------
    cudaStreamWaitEvent(0, evJoin, 0);
    agg_csr_kernel<64>
        <<<nb((long long)N * 32, T), T>>>(rowptr, esrc, asb, adb, h1, b1, x1, N);

    // ---------- layer 2 (H=32) ----------
    gemm_fused_kernel<128, 32, 32, 4, 8>
        <<<nb(N, 128), dim3(4, 32)>>>(x1, W2, h2, N, 64, as2, ad2, asb, adb);
    agg_csr_kernel<32>
        <<<nb((long long)N * 32, T), T>>>(rowptr, esrc, asb, adb, h2, b2, x2, N);

    // ---------- head ----------
    final_kernel<<<nb(N, T), T>>>(x2, Wfc, bfc, out, N);
}

// round 8
// speedup vs baseline: 2.4135x; 1.3391x over previous
#include <cuda_runtime.h>
#include <cuda_bf16.h>
#include <cstdint>

#define NN 100000
#define EMAXC 1700000

// ---------------- scratch (static device globals; no allocs) ----------------
__device__ float g_h1[NN * 64];
__device__ float g_x1[NN * 64];
__device__ float g_h2[NN * 32];
__device__ float g_x2[NN * 32];
__device__ float g_as[NN];
__device__ float g_ad[NN];
__device__ int   g_deg[NN];
__device__ int   g_rowptr[NN + 1];
__device__ int   g_cur[NN];
__device__ int   g_blk[128];
__device__ int   g_esrc[EMAXC];
__device__ uint4 g_bf[4096];   // preconverted W1 fragments: [kk16][n64][tig4]

typedef unsigned long long u64;

__device__ __forceinline__ u64 ffma2(u64 a, u64 b, u64 c) {
    u64 d;
    asm("fma.rn.f32x2 %0, %1, %2, %3;" : "=l"(d) : "l"(a), "l"(b), "l"(c));
    return d;
}
__device__ __forceinline__ u64 pack2(float x, float y) {
    u64 r;
    asm("mov.b64 %0, {%1,%2};" : "=l"(r) : "f"(x), "f"(y));
    return r;
}
__device__ __forceinline__ void unpack2(u64 v, float& x, float& y) {
    asm("mov.b64 {%0,%1}, %2;" : "=f"(x), "=f"(y) : "l"(v));
}

// ================= gemm1 via mma.sync, smem-free (bf16 split) ===============
__device__ __forceinline__ void mma16816(float* c, uint32_t a0, uint32_t a1,
                                         uint32_t a2, uint32_t a3,
                                         uint32_t b0, uint32_t b1) {
    asm volatile(
        "mma.sync.aligned.m16n8k16.row.col.f32.bf16.bf16.f32 "
        "{%0,%1,%2,%3}, {%4,%5,%6,%7}, {%8,%9}, {%0,%1,%2,%3};"
        : "+f"(c[0]), "+f"(c[1]), "+f"(c[2]), "+f"(c[3])
        : "r"(a0), "r"(a1), "r"(a2), "r"(a3), "r"(b0), "r"(b1));
}

__device__ __forceinline__ uint32_t bfhi2(float x, float y) {
    __nv_bfloat162 h = __floats2bfloat162_rn(x, y);
    return *(uint32_t*)&h;
}
__device__ __forceinline__ uint32_t bflo2(float x, float y, uint32_t hi) {
    __nv_bfloat162 h = *(__nv_bfloat162*)&hi;
    float2 f = __bfloat1622float2(h);
    __nv_bfloat162 l = __floats2bfloat162_rn(x - f.x, y - f.y);
    return *(uint32_t*)&l;
}

// precompute W1 fragments: idx = kk*256 + n*4 + tig
__global__ void preconv_b_kernel(const float* __restrict__ W,
                                 uint4* __restrict__ Bf) {
    int idx = blockIdx.x * 256 + threadIdx.x;
    if (idx >= 4096) return;
    int tig = idx & 3, n = (idx >> 2) & 63, kk = idx >> 8;
    int k = kk * 16 + 2 * tig;
    float w00 = __ldg(&W[(size_t)k * 64 + n]);
    float w01 = __ldg(&W[(size_t)(k + 1) * 64 + n]);
    float w10 = __ldg(&W[(size_t)(k + 8) * 64 + n]);
    float w11 = __ldg(&W[(size_t)(k + 9) * 64 + n]);
    uint4 o;
    o.x = bfhi2(w00, w01);
    o.y = bfhi2(w10, w11);
    o.z = bflo2(w00, w01, o.x);
    o.w = bflo2(w10, w11, o.y);
    Bf[idx] = o;
}

// h1[M,64] = x[M,256] @ W1[256,64]; alpha epilogue. 256 thr, no smem.
__global__ void __launch_bounds__(256)
gemm1_mma_kernel(const float* __restrict__ A,   // [M,256]
                 const uint4* __restrict__ Bf,  // preconverted fragments
                 float* __restrict__ C,         // [M,64]
                 int M,
                 const float* __restrict__ av, const float* __restrict__ bv,
                 float* __restrict__ as_out, float* __restrict__ ad_out) {
    const int tid = threadIdx.x;
    const int wid = tid >> 5, lane = tid & 31;
    const int gid = lane >> 2, tig = lane & 3;
    const int rowBase = blockIdx.x * 128;

    const int grLo = rowBase + wid * 16 + gid;
    const int grHi = grLo + 8;
    const float* a0p = A + (size_t)min(grLo, M - 1) * 256 + 2 * tig;
    const float* a1p = A + (size_t)min(grHi, M - 1) * 256 + 2 * tig;

    float acc[8][4];
#pragma unroll
    for (int t = 0; t < 8; t++)
#pragma unroll
        for (int j = 0; j < 4; j++) acc[t][j] = 0.f;

#pragma unroll 4
    for (int kk = 0; kk < 16; kk++) {
        float2 v00 = __ldg((const float2*)(a0p + kk * 16));
        float2 v01 = __ldg((const float2*)(a0p + kk * 16 + 8));
        float2 v10 = __ldg((const float2*)(a1p + kk * 16));
        float2 v11 = __ldg((const float2*)(a1p + kk * 16 + 8));
        uint32_t ah0 = bfhi2(v00.x, v00.y), ah1 = bfhi2(v10.x, v10.y);
        uint32_t ah2 = bfhi2(v01.x, v01.y), ah3 = bfhi2(v11.x, v11.y);
        uint32_t al0 = bflo2(v00.x, v00.y, ah0), al1 = bflo2(v10.x, v10.y, ah1);
        uint32_t al2 = bflo2(v01.x, v01.y, ah2), al3 = bflo2(v11.x, v11.y, ah3);
        const uint4* bp = Bf + kk * 256 + gid * 4 + tig;
#pragma unroll
        for (int nt = 0; nt < 8; nt++) {
            uint4 b = __ldg(bp + nt * 32);
            mma16816(acc[nt], ah0, ah1, ah2, ah3, b.x, b.y);  // hi*hi
            mma16816(acc[nt], ah0, ah1, ah2, ah3, b.z, b.w);  // hi*lo
            mma16816(acc[nt], al0, al1, al2, al3, b.x, b.y);  // lo*hi
        }
    }

    // ---- epilogue: store C rows + alpha dots ----
    float sLo = 0.f, dLo = 0.f, sHi = 0.f, dHi = 0.f;
#pragma unroll
    for (int nt = 0; nt < 8; nt++) {
        int col = nt * 8 + 2 * tig;
        float a0 = __ldg(&av[col]), a1 = __ldg(&av[col + 1]);
        float b0 = __ldg(&bv[col]), b1 = __ldg(&bv[col + 1]);
        if (grLo < M)
            *(float2*)(C + (size_t)grLo * 64 + col) = make_float2(acc[nt][0], acc[nt][1]);
        if (grHi < M)
            *(float2*)(C + (size_t)grHi * 64 + col) = make_float2(acc[nt][2], acc[nt][3]);
        sLo += acc[nt][0] * a0 + acc[nt][1] * a1;
        dLo += acc[nt][0] * b0 + acc[nt][1] * b1;
        sHi += acc[nt][2] * a0 + acc[nt][3] * a1;
        dHi += acc[nt][2] * b0 + acc[nt][3] * b1;
    }
#pragma unroll
    for (int off = 1; off < 4; off <<= 1) {
        sLo += __shfl_xor_sync(0xffffffffu, sLo, off);
        dLo += __shfl_xor_sync(0xffffffffu, dLo, off);
        sHi += __shfl_xor_sync(0xffffffffu, sHi, off);
        dHi += __shfl_xor_sync(0xffffffffu, dHi, off);
    }
    if (tig == 0) {
        if (grLo < M) { as_out[grLo] = sLo; ad_out[grLo] = dLo; }
        if (grHi < M) { as_out[grHi] = sHi; ad_out[grHi] = dHi; }
    }
}

// ======================= CSR build =======================
__global__ void hist_kernel(const int* __restrict__ ei, int E, int nE,
                            int* __restrict__ deg) {
    int e = blockIdx.x * blockDim.x + threadIdx.x;
    if (e >= nE) return;
    int d = (e < E) ? __ldg(&ei[E + e]) : e - E;
    atomicAdd(&deg[d], 1);
}

__global__ void scan_block_kernel(const int* __restrict__ deg,
                                  int* __restrict__ rowptr,
                                  int* __restrict__ blk, int n) {
    __shared__ int sh[1024];
    int i = blockIdx.x * 1024 + threadIdx.x;
    int v = (i < n) ? deg[i] : 0;
    sh[threadIdx.x] = v;
    __syncthreads();
#pragma unroll
    for (int off = 1; off < 1024; off <<= 1) {
        int t = (threadIdx.x >= off) ? sh[threadIdx.x - off] : 0;
        __syncthreads();
        sh[threadIdx.x] += t;
        __syncthreads();
    }
    if (i < n) rowptr[i + 1] = sh[threadIdx.x];
    if (threadIdx.x == 1023) blk[blockIdx.x] = sh[1023];
}

__global__ void scan_tops_kernel(int* __restrict__ blk, int nb) {
    __shared__ int sh[128];
    int v = (threadIdx.x < nb) ? blk[threadIdx.x] : 0;
    sh[threadIdx.x] = v;
    __syncthreads();
#pragma unroll
    for (int off = 1; off < 128; off <<= 1) {
        int t = (threadIdx.x >= off) ? sh[threadIdx.x - off] : 0;
        __syncthreads();
        sh[threadIdx.x] += t;
        __syncthreads();
    }
    if (threadIdx.x < nb)
        blk[threadIdx.x] = (threadIdx.x == 0) ? 0 : sh[threadIdx.x - 1];
}

__global__ void scan_add_kernel(int* __restrict__ rowptr,
                                const int* __restrict__ blk,
                                const int* __restrict__ deg,
                                int* __restrict__ cur, int n) {
    int i = blockIdx.x * 1024 + threadIdx.x;
    if (i >= n) return;
    int v = rowptr[i + 1] + blk[i / 1024];
    rowptr[i + 1] = v;
    cur[i] = v - deg[i];
    if (i == 0) rowptr[0] = 0;
}

__global__ void scatter_kernel(const int* __restrict__ ei, int E, int nE,
                               int* __restrict__ cur, int* __restrict__ esrc) {
    int e = blockIdx.x * blockDim.x + threadIdx.x;
    if (e >= nE) return;
    int s, d;
    if (e < E) { s = __ldg(&ei[e]); d = __ldg(&ei[E + e]); } else { s = d = e - E; }
    int p = atomicAdd(&cur[d], 1);
    esrc[p] = s;
}

// ---------------- FFMA2 GEMM (layer 2): C[M,BN] = A[M,K] @ B[K,BN] ---------
template <int BM, int BN, int BK, int TM, int TN>
__global__ void gemm_fused_kernel(const float* __restrict__ A,
                                  const float* __restrict__ B,
                                  float* __restrict__ C, int M, int K,
                                  const float* __restrict__ av,
                                  const float* __restrict__ bv,
                                  float* __restrict__ as_out,
                                  float* __restrict__ ad_out) {
    __shared__ u64  As[BK][BM + 1];
    __shared__ float Bs[BK][BN];
    const int tx = threadIdx.x, ty = threadIdx.y;
    constexpr int TG = BN / TN;
    const int tid = ty * TG + tx;
    constexpr int NT = TG * (BM / TM);
    const int rowBase = blockIdx.x * BM;

    u64 acc[TM][TN / 2];
#pragma unroll
    for (int i = 0; i < TM; i++)
#pragma unroll
        for (int j = 0; j < TN / 2; j++) acc[i][j] = 0ull;

    for (int k0 = 0; k0 < K; k0 += BK) {
#pragma unroll
        for (int it = tid; it < BM * BK / 4; it += NT) {
            int r = (it * 4) / BK, c = (it * 4) % BK;
            int gr = rowBase + r;
            float4 v = make_float4(0.f, 0.f, 0.f, 0.f);
            if (gr < M) v = *(const float4*)(A + (size_t)gr * K + k0 + c);
            As[c + 0][r] = pack2(v.x, v.x);
            As[c + 1][r] = pack2(v.y, v.y);
            As[c + 2][r] = pack2(v.z, v.z);
            As[c + 3][r] = pack2(v.w, v.w);
        }
#pragma unroll
        for (int it = tid; it < BK * BN / 4; it += NT) {
            int r = (it * 4) / BN, c = (it * 4) % BN;
            *(float4*)&Bs[r][c] = *(const float4*)(B + (size_t)(k0 + r) * BN + c);
        }
        __syncthreads();
#pragma unroll
        for (int k = 0; k < BK; k++) {
            u64 ra[TM], rb[TN / 2];
#pragma unroll
            for (int i = 0; i < TM; i++) ra[i] = As[k][ty * TM + i];
#pragma unroll
            for (int j = 0; j < TN / 2; j++)
                rb[j] = *(const u64*)&Bs[k][tx * TN + 2 * j];
#pragma unroll
            for (int i = 0; i < TM; i++)
#pragma unroll
                for (int j = 0; j < TN / 2; j++)
                    acc[i][j] = ffma2(ra[i], rb[j], acc[i][j]);
        }
        __syncthreads();
    }

    float avr[TN], bvr[TN];
#pragma unroll
    for (int j = 0; j < TN; j++) {
        avr[j] = av[tx * TN + j];
        bvr[j] = bv[tx * TN + j];
    }

#pragma unroll
    for (int i = 0; i < TM; i++) {
        int gr = rowBase + ty * TM + i;
        float f[TN];
#pragma unroll
        for (int j = 0; j < TN / 2; j++) unpack2(acc[i][j], f[2 * j], f[2 * j + 1]);
        if (gr < M) {
            *(float4*)(C + (size_t)gr * BN + tx * TN) =
                make_float4(f[0], f[1], f[2], f[3]);
            *(float4*)(C + (size_t)gr * BN + tx * TN + 4) =
                make_float4(f[4], f[5], f[6], f[7]);
        }
        float s = 0.f, d = 0.f;
#pragma unroll
        for (int j = 0; j < TN; j++) {
            s += f[j] * avr[j];
            d += f[j] * bvr[j];
        }
#pragma unroll
        for (int off = TG / 2; off > 0; off >>= 1) {
            s += __shfl_xor_sync(0xffffffffu, s, off);
            d += __shfl_xor_sync(0xffffffffu, d, off);
        }
        if (tx == 0 && gr < M) {
            as_out[gr] = s;
            ad_out[gr] = d;
        }
    }
}

// ======== CSR gather aggregation: one warp per node, fused norm+bias+relu ===
template <int H>
__global__ void agg_csr_kernel(const int* __restrict__ rowptr,
                               const int* __restrict__ esrc,
                               const float* __restrict__ as,
                               const float* __restrict__ ad,
                               const float* __restrict__ h,
                               const float* __restrict__ bias,
                               float* __restrict__ out, int n) {
    constexpr int G = H / 4;
    constexpr int EPW = 32 / G;
    int warp = (blockIdx.x * blockDim.x + threadIdx.x) >> 5;
    if (warp >= n) return;
    int lane = threadIdx.x & 31;
    int eslot = lane / G;
    int part = lane % G;

    int beg = __ldg(&rowptr[warp]);
    int end = __ldg(&rowptr[warp + 1]);
    float add = __ldg(&ad[warp]);

    float4 acc = make_float4(0.f, 0.f, 0.f, 0.f);
    float den = 0.f;
    for (int i = beg + eslot; i < end; i += EPW) {
        int s = __ldg(&esrc[i]);
        float v = __ldg(&as[s]) + add;
        v = (v > 0.f) ? v : 0.2f * v;
        float w = __expf(v);
        float4 hv = __ldg(&((const float4*)(h + (size_t)s * H))[part]);
        acc.x += w * hv.x; acc.y += w * hv.y;
        acc.z += w * hv.z; acc.w += w * hv.w;
        den += w;
    }
#pragma unroll
    for (int off = G; off < 32; off <<= 1) {
        acc.x += __shfl_xor_sync(0xffffffffu, acc.x, off);
        acc.y += __shfl_xor_sync(0xffffffffu, acc.y, off);
        acc.z += __shfl_xor_sync(0xffffffffu, acc.z, off);
        acc.w += __shfl_xor_sync(0xffffffffu, acc.w, off);
        den   += __shfl_xor_sync(0xffffffffu, den, off);
    }
    if (eslot == 0) {
        float inv = 1.f / den;
        float4 b = __ldg(&((const float4*)bias)[part]);
        float4 o;
        o.x = fmaxf(acc.x * inv + b.x, 0.f);
        o.y = fmaxf(acc.y * inv + b.y, 0.f);
        o.z = fmaxf(acc.z * inv + b.z, 0.f);
        o.w = fmaxf(acc.w * inv + b.w, 0.f);
        ((float4*)(out + (size_t)warp * H))[part] = o;
    }
}

// ---------------- final head ----------------
__global__ void final_kernel(const float* __restrict__ x2,
                             const float* __restrict__ Wfc,
                             const float* __restrict__ bfc,
                             float* __restrict__ out, int n) {
    int i = blockIdx.x * blockDim.x + threadIdx.x;
    if (i >= n) return;
    const float4* hp = (const float4*)(x2 + (size_t)i * 32);
    float s = 0.f;
#pragma unroll
    for (int j = 0; j < 8; j++) {
        float4 a = hp[j];
        float4 w = ((const float4*)Wfc)[j];
        s += a.x * w.x + a.y * w.y + a.z * w.z + a.w * w.w;
    }
    out[i] = s + bfc[0];
}

// ---------------- launch ----------------
extern "C" void kernel_launch(void* const* d_in, const int* in_sizes, int n_in,
                              void* d_out, int out_size) {
    const float* x   = (const float*)d_in[0];
    const int*   ei  = (const int*)d_in[1];
    const float* W1  = (const float*)d_in[2];
    const float* as1 = (const float*)d_in[3];
    const float* ad1 = (const float*)d_in[4];
    const float* b1  = (const float*)d_in[5];
    const float* W2  = (const float*)d_in[6];
    const float* as2 = (const float*)d_in[7];
    const float* ad2 = (const float*)d_in[8];
    const float* b2  = (const float*)d_in[9];
    const float* Wfc = (const float*)d_in[10];
    const float* bfc = (const float*)d_in[11];
    float* out = (float*)d_out;

    const int N  = in_sizes[0] / 256;
    const int E  = in_sizes[1] / 2;
    const int ET = E + N;

    float *h1, *x1, *h2, *x2, *asb, *adb;
    int *deg, *rowptr, *cur, *blk, *esrc;
    uint4* bf;
    cudaGetSymbolAddress((void**)&h1, g_h1);
    cudaGetSymbolAddress((void**)&x1, g_x1);
    cudaGetSymbolAddress((void**)&h2, g_h2);
    cudaGetSymbolAddress((void**)&x2, g_x2);
    cudaGetSymbolAddress((void**)&asb, g_as);
    cudaGetSymbolAddress((void**)&adb, g_ad);
    cudaGetSymbolAddress((void**)&deg, g_deg);
    cudaGetSymbolAddress((void**)&rowptr, g_rowptr);
    cudaGetSymbolAddress((void**)&cur, g_cur);
    cudaGetSymbolAddress((void**)&blk, g_blk);
    cudaGetSymbolAddress((void**)&esrc, g_esrc);
    cudaGetSymbolAddress((void**)&bf, g_bf);

    static cudaStream_t s2 = nullptr;
    static cudaEvent_t evFork = nullptr, evJoin = nullptr;
    if (!s2) {
        cudaStreamCreateWithFlags(&s2, cudaStreamNonBlocking);
        cudaEventCreateWithFlags(&evFork, cudaEventDisableTiming);
        cudaEventCreateWithFlags(&evJoin, cudaEventDisableTiming);
    }

    const int T = 256;
    auto nb = [](long long n, int t) { return (int)((n + t - 1) / t); };
    const int nScanBlk = nb(N, 1024);

    // ---------- fork: CSR build starts on side stream ----------
    cudaEventRecord(evFork, 0);
    cudaStreamWaitEvent(s2, evFork, 0);
    cudaMemsetAsync(deg, 0, (size_t)N * sizeof(int), s2);
    hist_kernel<<<nb(ET, T), T, 0, s2>>>(ei, E, ET, deg);               // 1
    scan_block_kernel<<<nScanBlk, 1024, 0, s2>>>(deg, rowptr, blk, N);  // 2

    // ---------- main stream: preconvert W1, then mma gemm1 (4th launch) ----
    preconv_b_kernel<<<16, 256>>>(W1, bf);                              // 3
    gemm1_mma_kernel<<<nb(N, 128), 256>>>(x, bf, h1, N, as1, ad1,
                                          asb, adb);                    // 4

    // ---------- side stream: rest of CSR build ----------
    scan_tops_kernel<<<1, 128, 0, s2>>>(blk, nScanBlk);                 // 5
    scan_add_kernel<<<nScanBlk, 1024, 0, s2>>>(rowptr, blk, deg, cur, N); // 6
    scatter_kernel<<<nb(ET, T), T, 0, s2>>>(ei, E, ET, cur, esrc);      // 7
    cudaEventRecord(evJoin, s2);

    // ---------- join, then aggregation ----------
    cudaStreamWaitEvent(0, evJoin, 0);
    agg_csr_kernel<64>
        <<<nb((long long)N * 32, T), T>>>(rowptr, esrc, asb, adb, h1, b1, x1, N);

    // ---------- layer 2 (H=32) ----------
    gemm_fused_kernel<128, 32, 32, 4, 8>
        <<<nb(N, 128), dim3(4, 32)>>>(x1, W2, h2, N, 64, as2, ad2, asb, adb);
    agg_csr_kernel<32>
        <<<nb((long long)N * 32, T), T>>>(rowptr, esrc, asb, adb, h2, b2, x2, N);

    // ---------- head ----------
    final_kernel<<<nb(N, T), T>>>(x2, Wfc, bfc, out, N);
}